// round 1
// baseline (speedup 1.0000x reference)
#include <cuda_runtime.h>
#include <cstdint>

#define D 128
#define MAXN 100000
#define TILE_M 128
#define KT 32
#define PAD 132

// ---------------- scratch (device globals; no allocations allowed) ----------
__device__ float g_deg[MAXN];                       // degree -> reciprocal
__device__ float g_xl [(size_t)MAXN * D];           // x @ Wl^T (per layer)
__device__ float g_agg[(size_t)MAXN * D];           // scatter accumulator
__device__ float g_h  [(size_t)MAXN * D];           // layer-1 hidden
__device__ int   g_is64;                            // edge index dtype flag

// ---------------- helpers ---------------------------------------------------
__device__ __forceinline__ int load_idx(const void* p, int is64, long long i) {
    if (is64) return (int)((const long long*)p)[i];
    return ((const int*)p)[i];
}

// Probe whether edge_index is int64 (high 32-bit words all zero) or int32.
__global__ void probe_idx_kernel(const void* idx) {
    if (threadIdx.x == 0 && blockIdx.x == 0) {
        const unsigned int* w = (const unsigned int*)idx;
        int all0 = 1;
        for (int i = 0; i < 128; i++) {
            if (w[2 * i + 1] != 0u) { all0 = 0; break; }
        }
        g_is64 = all0;
    }
}

// Zero agg (N*D floats) and deg (N floats).
__global__ void zero_kernel(int N) {
    long long total4 = (long long)N * (D / 4);
    long long stride = (long long)gridDim.x * blockDim.x;
    float4 z = make_float4(0.f, 0.f, 0.f, 0.f);
    for (long long i = blockIdx.x * (long long)blockDim.x + threadIdx.x;
         i < total4; i += stride) {
        ((float4*)g_agg)[i] = z;
        if (i < N) g_deg[i] = 0.f;
    }
}

// deg[dst] += 1 per edge.
__global__ void deg_kernel(const void* __restrict__ edge, int E) {
    int is64 = g_is64;
    long long stride = (long long)gridDim.x * blockDim.x;
    for (long long e = blockIdx.x * (long long)blockDim.x + threadIdx.x;
         e < E; e += stride) {
        int d = load_idx(edge, is64, (long long)E + e);
        atomicAdd(&g_deg[d], 1.0f);
    }
}

// deg -> 1 / max(deg, 1)
__global__ void invdeg_kernel(int N) {
    int i = blockIdx.x * blockDim.x + threadIdx.x;
    if (i < N) g_deg[i] = 1.0f / fmaxf(g_deg[i], 1.0f);
}

// ---------------- GEMM: C[N,128] = A[N,128] @ W[128,128]^T (+ bias) ---------
// 128x128 block tile, 8x8 micro-tile per thread, k-major smem (conflict-free
// float4 compute loads, PAD=132 keeps 16B alignment of each k-row).
__global__ __launch_bounds__(256, 2)
void gemm_nt_kernel(const float* __restrict__ A, const float* __restrict__ W,
                    const float* __restrict__ bias, float* __restrict__ C,
                    int N) {
    __shared__ float As[KT][PAD];
    __shared__ float Ws[KT][PAD];

    const int t  = threadIdx.x;
    const int tx = t & 15;        // col group 0..15
    const int ty = t >> 4;        // row group 0..15
    const int row0 = blockIdx.x * TILE_M;

    const int lr = t >> 3;        // 0..31 : row within 32-row load slab
    const int lc = t & 7;         // 0..7  : float4 chunk along k

    float acc[8][8];
#pragma unroll
    for (int i = 0; i < 8; i++)
#pragma unroll
        for (int j = 0; j < 8; j++) acc[i][j] = 0.f;

    for (int k0 = 0; k0 < D; k0 += KT) {
#pragma unroll
        for (int it = 0; it < 4; it++) {
            int r = lr + 32 * it;                 // 0..127
            int gr = row0 + r;
            float4 av = make_float4(0.f, 0.f, 0.f, 0.f);
            if (gr < N)
                av = *(const float4*)(A + (size_t)gr * D + k0 + lc * 4);
            As[lc * 4 + 0][r] = av.x;
            As[lc * 4 + 1][r] = av.y;
            As[lc * 4 + 2][r] = av.z;
            As[lc * 4 + 3][r] = av.w;

            float4 wv = *(const float4*)(W + (size_t)r * D + k0 + lc * 4);
            Ws[lc * 4 + 0][r] = wv.x;
            Ws[lc * 4 + 1][r] = wv.y;
            Ws[lc * 4 + 2][r] = wv.z;
            Ws[lc * 4 + 3][r] = wv.w;
        }
        __syncthreads();

#pragma unroll
        for (int kk = 0; kk < KT; kk++) {
            float4 a0 = *(const float4*)&As[kk][ty * 8];
            float4 a1 = *(const float4*)&As[kk][ty * 8 + 4];
            float4 w0 = *(const float4*)&Ws[kk][tx * 8];
            float4 w1 = *(const float4*)&Ws[kk][tx * 8 + 4];
            float a[8] = {a0.x, a0.y, a0.z, a0.w, a1.x, a1.y, a1.z, a1.w};
            float w[8] = {w0.x, w0.y, w0.z, w0.w, w1.x, w1.y, w1.z, w1.w};
#pragma unroll
            for (int i = 0; i < 8; i++)
#pragma unroll
                for (int j = 0; j < 8; j++)
                    acc[i][j] = fmaf(a[i], w[j], acc[i][j]);
        }
        __syncthreads();
    }

    float bv[8];
#pragma unroll
    for (int j = 0; j < 8; j++) bv[j] = bias ? bias[tx * 8 + j] : 0.f;

#pragma unroll
    for (int i = 0; i < 8; i++) {
        int gr = row0 + ty * 8 + i;
        if (gr < N) {
            float* cp = C + (size_t)gr * D + tx * 8;
            float4 o0, o1;
            o0.x = acc[i][0] + bv[0]; o0.y = acc[i][1] + bv[1];
            o0.z = acc[i][2] + bv[2]; o0.w = acc[i][3] + bv[3];
            o1.x = acc[i][4] + bv[4]; o1.y = acc[i][5] + bv[5];
            o1.z = acc[i][6] + bv[6]; o1.w = acc[i][7] + bv[7];
            *(float4*)(cp)     = o0;
            *(float4*)(cp + 4) = o1;
        }
    }
}

// ---------------- edge scatter: agg[dst] += xl[src], warp per edge ---------
__global__ void scatter_kernel(const void* __restrict__ edge, int E) {
    int is64 = g_is64;
    int lane = threadIdx.x & 31;
    long long warpId = (blockIdx.x * (long long)blockDim.x + threadIdx.x) >> 5;
    long long nWarps = ((long long)gridDim.x * blockDim.x) >> 5;

    for (long long e = warpId; e < E; e += nWarps) {
        int s = load_idx(edge, is64, e);
        int d = load_idx(edge, is64, (long long)E + e);
        float4 v = *(const float4*)(g_xl + (size_t)s * D + lane * 4);
        float* p = g_agg + (size_t)d * D + lane * 4;
#if __CUDA_ARCH__ >= 900
        atomicAdd((float4*)p, v);
#else
        atomicAdd(p + 0, v.x); atomicAdd(p + 1, v.y);
        atomicAdd(p + 2, v.z); atomicAdd(p + 3, v.w);
#endif
    }
}

// ---------------- combine: out += agg * invdeg, optional relu / agg reset --
__global__ void combine_kernel(float* __restrict__ outb, int N,
                               int doRelu, int resetAgg) {
    long long total4 = (long long)N * (D / 4);
    long long stride = (long long)gridDim.x * blockDim.x;
    float4 z = make_float4(0.f, 0.f, 0.f, 0.f);
    for (long long i = blockIdx.x * (long long)blockDim.x + threadIdx.x;
         i < total4; i += stride) {
        int row = (int)(i >> 5);                  // 32 float4 per row
        float inv = g_deg[row];
        float4 a = ((const float4*)g_agg)[i];
        float4 o = ((float4*)outb)[i];
        o.x += a.x * inv; o.y += a.y * inv;
        o.z += a.z * inv; o.w += a.w * inv;
        if (doRelu) {
            o.x = fmaxf(o.x, 0.f); o.y = fmaxf(o.y, 0.f);
            o.z = fmaxf(o.z, 0.f); o.w = fmaxf(o.w, 0.f);
        }
        ((float4*)outb)[i] = o;
        if (resetAgg) ((float4*)g_agg)[i] = z;
    }
}

// ---------------- launch ----------------------------------------------------
extern "C" void kernel_launch(void* const* d_in, const int* in_sizes, int n_in,
                              void* d_out, int out_size) {
    const float* x    = (const float*)d_in[0];
    const void*  edge = d_in[1];
    const float* Wl1  = (const float*)d_in[2];
    const float* Wr1  = (const float*)d_in[3];
    const float* b1   = (const float*)d_in[4];
    const float* Wl2  = (const float*)d_in[5];
    const float* Wr2  = (const float*)d_in[6];
    const float* b2   = (const float*)d_in[7];
    float* out = (float*)d_out;

    const int N = in_sizes[0] / D;
    const int E = in_sizes[1] / 2;

    float *xl, *agg_p, *h;
    cudaGetSymbolAddress((void**)&xl,    g_xl);
    cudaGetSymbolAddress((void**)&agg_p, g_agg);
    cudaGetSymbolAddress((void**)&h,     g_h);
    (void)agg_p;

    const int gemmGrid = (N + TILE_M - 1) / TILE_M;

    probe_idx_kernel<<<1, 32>>>(edge);
    zero_kernel<<<2048, 256>>>(N);
    deg_kernel<<<2048, 256>>>(edge, E);
    invdeg_kernel<<<(N + 255) / 256, 256>>>(N);

    // ---- layer 1 ----
    gemm_nt_kernel<<<gemmGrid, 256>>>(x, Wl1, nullptr, xl, N);  // xl = x@Wl1^T
    gemm_nt_kernel<<<gemmGrid, 256>>>(x, Wr1, b1, h, N);        // h  = x@Wr1^T + b1
    scatter_kernel<<<4096, 256>>>(edge, E);                     // agg += xl[src]
    combine_kernel<<<2048, 256>>>(h, N, /*relu=*/1, /*reset=*/1);

    // ---- layer 2 ----
    gemm_nt_kernel<<<gemmGrid, 256>>>(h, Wl2, nullptr, xl, N);  // xl = h@Wl2^T
    gemm_nt_kernel<<<gemmGrid, 256>>>(h, Wr2, b2, out, N);      // out = h@Wr2^T + b2
    scatter_kernel<<<4096, 256>>>(edge, E);                     // agg += xl[src]
    combine_kernel<<<2048, 256>>>(out, N, /*relu=*/0, /*reset=*/0);
}

// round 3
// speedup vs baseline: 1.2660x; 1.2660x over previous
#include <cuda_runtime.h>
#include <cuda_bf16.h>
#include <cstdint>

#define D 128
#define MAXN 100000
#define MAXTILES ((MAXN + 127) / 128)   // 782

// ---------------- scratch (device globals; no allocations allowed) ----------
__device__ float g_deg[MAXN];
__device__ float g_xl [(size_t)MAXN * D];
__device__ float g_agg[(size_t)MAXN * D];
__device__ float g_h  [(size_t)MAXN * D];
__device__ int   g_is64;
// bf16 hi/lo staging, plain row-major [row][128] bf16 (16 uint4 per row)
__device__ uint4 g_ah[(size_t)MAXTILES * 2048];
__device__ uint4 g_al[(size_t)MAXTILES * 2048];
__device__ uint4 g_wh[2 * 4096];   // per layer: [Wl;Wr] stacked = 256 rows
__device__ uint4 g_wl[2 * 4096];

// ---------------- small helpers ---------------------------------------------
__device__ __forceinline__ int load_idx(const void* p, int is64, long long i) {
    if (is64) return (int)((const long long*)p)[i];
    return ((const int*)p)[i];
}

__global__ void probe_idx_kernel(const void* idx) {
    if (threadIdx.x == 0 && blockIdx.x == 0) {
        const unsigned int* w = (const unsigned int*)idx;
        int all0 = 1;
        for (int i = 0; i < 128; i++)
            if (w[2 * i + 1] != 0u) { all0 = 0; break; }
        g_is64 = all0;
    }
}

__global__ void zero_kernel(int N) {
    long long total4 = (long long)N * (D / 4);
    long long stride = (long long)gridDim.x * blockDim.x;
    float4 z = make_float4(0.f, 0.f, 0.f, 0.f);
    for (long long i = blockIdx.x * (long long)blockDim.x + threadIdx.x;
         i < total4; i += stride) {
        ((float4*)g_agg)[i] = z;
        if (i < N) g_deg[i] = 0.f;
    }
}

__global__ void deg_kernel(const void* __restrict__ edge, int E) {
    int is64 = g_is64;
    long long stride = (long long)gridDim.x * blockDim.x;
    for (long long e = blockIdx.x * (long long)blockDim.x + threadIdx.x;
         e < E; e += stride) {
        int d = load_idx(edge, is64, (long long)E + e);
        atomicAdd(&g_deg[d], 1.0f);
    }
}

__global__ void invdeg_kernel(int N) {
    int i = blockIdx.x * blockDim.x + threadIdx.x;
    if (i < N) g_deg[i] = 1.0f / fmaxf(g_deg[i], 1.0f);
}

// ---------------- fp32 -> bf16 hi/lo, plain row-major ------------------------
// chunk c: row = c>>4, kc = c&15 -> 8 floats at A[row*128 + kc*8]
__global__ void conv_kernel(const float* __restrict__ A, int Nrows,
                            long long totalChunks,
                            uint4* __restrict__ oh, uint4* __restrict__ ol) {
    long long stride = (long long)gridDim.x * blockDim.x;
    for (long long c = blockIdx.x * (long long)blockDim.x + threadIdx.x;
         c < totalChunks; c += stride) {
        int row = (int)(c >> 4);
        int kc  = (int)(c & 15);
        float v[8];
        if (row < Nrows) {
            const float4* ap = (const float4*)(A + (size_t)row * D + kc * 8);
            float4 a = ap[0], b = ap[1];
            v[0]=a.x; v[1]=a.y; v[2]=a.z; v[3]=a.w;
            v[4]=b.x; v[5]=b.y; v[6]=b.z; v[7]=b.w;
        } else {
#pragma unroll
            for (int i = 0; i < 8; i++) v[i] = 0.f;
        }
        unsigned int hw[4], lw[4];
#pragma unroll
        for (int i = 0; i < 4; i++) {
            float f0 = v[2*i], f1 = v[2*i+1];
            __nv_bfloat16 h0 = __float2bfloat16(f0);
            __nv_bfloat16 h1 = __float2bfloat16(f1);
            __nv_bfloat16 l0 = __float2bfloat16(f0 - __bfloat162float(h0));
            __nv_bfloat16 l1 = __float2bfloat16(f1 - __bfloat162float(h1));
            hw[i] = (unsigned int)__bfloat16_as_ushort(h0) |
                    ((unsigned int)__bfloat16_as_ushort(h1) << 16);
            lw[i] = (unsigned int)__bfloat16_as_ushort(l0) |
                    ((unsigned int)__bfloat16_as_ushort(l1) << 16);
        }
        oh[c] = make_uint4(hw[0], hw[1], hw[2], hw[3]);
        lw[0] = lw[0]; // keep
        ol[c] = make_uint4(lw[0], lw[1], lw[2], lw[3]);
    }
}

// ---------------- mma.sync bf16 GEMM -----------------------------------------
// C[128 x 256] per CTA: cols 0..127 -> out0 = A@Wl^T, cols 128..255 -> out1 = A@Wr^T + b
// 3-term fp32 emulation: ah@wh + ah@wl + al@wh
__device__ __forceinline__ void mma16816(float* acc, const unsigned* a,
                                         const unsigned* b) {
    asm volatile(
        "mma.sync.aligned.m16n8k16.row.col.f32.bf16.bf16.f32 "
        "{%0,%1,%2,%3}, {%4,%5,%6,%7}, {%8,%9}, {%0,%1,%2,%3};"
        : "+f"(acc[0]), "+f"(acc[1]), "+f"(acc[2]), "+f"(acc[3])
        : "r"(a[0]), "r"(a[1]), "r"(a[2]), "r"(a[3]), "r"(b[0]), "r"(b[1]));
}

// SMEM row stride: 136 bf16 = 272 B = 68 b32 = 17 uint4 (16B aligned, conflict-free frags)
#define RS32 68
#define RS16 17
#define SM_A_H 0                       // 128 rows
#define SM_A_L (128 * RS32)            // b32 offsets
#define SM_W_H (256 * RS32)            // 256 rows
#define SM_W_L (SM_W_H + 256 * RS32)
#define SMEM_B32 (SM_W_L + 256 * RS32) // 768*68 = 52224 b32 = 208896 B

__global__ __launch_bounds__(512, 1)
void gemm_tc_kernel(const uint4* __restrict__ wh4, const uint4* __restrict__ wl4,
                    const float* __restrict__ bias,
                    float* __restrict__ out0, float* __restrict__ out1, int N) {
    extern __shared__ unsigned smem32[];
    uint4* smem4 = (uint4*)smem32;

    const int tid  = threadIdx.x;
    const int wid  = tid >> 5;
    const int lane = tid & 31;
    const int g = lane >> 2;          // 0..7
    const int q = lane & 3;           // 0..3
    const int tile = blockIdx.x;

    // warp tile: rows (wid%4)*32, cols (wid/4)*64
    const int mrow = (wid & 3) * 32;
    const int ncol = (wid >> 2) * 64;

    // ---- stage operands into SMEM (global row-major 16 uint4/row -> strided 17)
    {
        const uint4* ga = ((const uint4*)g_ah) + (size_t)tile * 2048;
        const uint4* gl = ((const uint4*)g_al) + (size_t)tile * 2048;
        for (int i = tid; i < 2048; i += 512) {
            int r = i >> 4, c = i & 15;
            smem4[(SM_A_H >> 2) + r * RS16 + c] = ga[i];
            smem4[(SM_A_L >> 2) + r * RS16 + c] = gl[i];
        }
        for (int i = tid; i < 4096; i += 512) {
            int r = i >> 4, c = i & 15;
            smem4[(SM_W_H >> 2) + r * RS16 + c] = wh4[i];
            smem4[(SM_W_L >> 2) + r * RS16 + c] = wl4[i];
        }
    }
    __syncthreads();

    float acc[2][8][4];
#pragma unroll
    for (int mt = 0; mt < 2; mt++)
#pragma unroll
        for (int nt = 0; nt < 8; nt++)
#pragma unroll
            for (int i = 0; i < 4; i++) acc[mt][nt][i] = 0.f;

#pragma unroll
    for (int kc = 0; kc < 8; kc++) {
        const int kb = kc * 8;        // b32 offset within row

        unsigned ah[2][4], al[2][4];
#pragma unroll
        for (int mt = 0; mt < 2; mt++) {
            int r = mrow + mt * 16 + g;
            ah[mt][0] = smem32[SM_A_H + r * RS32 + kb + q];
            ah[mt][1] = smem32[SM_A_H + (r + 8) * RS32 + kb + q];
            ah[mt][2] = smem32[SM_A_H + r * RS32 + kb + 4 + q];
            ah[mt][3] = smem32[SM_A_H + (r + 8) * RS32 + kb + 4 + q];
            al[mt][0] = smem32[SM_A_L + r * RS32 + kb + q];
            al[mt][1] = smem32[SM_A_L + (r + 8) * RS32 + kb + q];
            al[mt][2] = smem32[SM_A_L + r * RS32 + kb + 4 + q];
            al[mt][3] = smem32[SM_A_L + (r + 8) * RS32 + kb + 4 + q];
        }
        unsigned wh[8][2], wl[8][2];
#pragma unroll
        for (int nt = 0; nt < 8; nt++) {
            int n = ncol + nt * 8 + g;
            wh[nt][0] = smem32[SM_W_H + n * RS32 + kb + q];
            wh[nt][1] = smem32[SM_W_H + n * RS32 + kb + 4 + q];
            wl[nt][0] = smem32[SM_W_L + n * RS32 + kb + q];
            wl[nt][1] = smem32[SM_W_L + n * RS32 + kb + 4 + q];
        }
#pragma unroll
        for (int mt = 0; mt < 2; mt++)
#pragma unroll
            for (int nt = 0; nt < 8; nt++) {
                mma16816(acc[mt][nt], ah[mt], wh[nt]);
                mma16816(acc[mt][nt], ah[mt], wl[nt]);
                mma16816(acc[mt][nt], al[mt], wh[nt]);
            }
    }

    // ---- store ------------------------------------------------------------
    const int osel = (ncol >= 128);
    float* outp = osel ? out1 : out0;
    const int cbase = ncol - osel * 128;

#pragma unroll
    for (int nt = 0; nt < 8; nt++) {
        int col = cbase + nt * 8 + q * 2;
        float b0 = 0.f, b1 = 0.f;
        if (osel) { b0 = __ldg(bias + col); b1 = __ldg(bias + col + 1); }
#pragma unroll
        for (int mt = 0; mt < 2; mt++) {
            int r = tile * 128 + mrow + mt * 16 + g;
            if (r < N) {
                float2 v;
                v.x = acc[mt][nt][0] + b0;
                v.y = acc[mt][nt][1] + b1;
                *(float2*)(outp + (size_t)r * D + col) = v;
            }
            if (r + 8 < N) {
                float2 v;
                v.x = acc[mt][nt][2] + b0;
                v.y = acc[mt][nt][3] + b1;
                *(float2*)(outp + (size_t)(r + 8) * D + col) = v;
            }
        }
    }
}

// ---------------- edge scatter: agg[dst] += xl[src], warp per edge ----------
__global__ void scatter_kernel(const void* __restrict__ edge, int E) {
    int is64 = g_is64;
    int lane = threadIdx.x & 31;
    long long warpId = (blockIdx.x * (long long)blockDim.x + threadIdx.x) >> 5;
    long long nWarps = ((long long)gridDim.x * blockDim.x) >> 5;

    for (long long e = warpId; e < E; e += nWarps) {
        int s = load_idx(edge, is64, e);
        int d = load_idx(edge, is64, (long long)E + e);
        float4 v = *(const float4*)(g_xl + (size_t)s * D + lane * 4);
        float* p = g_agg + (size_t)d * D + lane * 4;
        atomicAdd((float4*)p, v);
    }
}

// ---------------- combine: out += agg * invdeg, optional relu / agg reset ---
__global__ void combine_kernel(float* __restrict__ outb, int N,
                               int doRelu, int resetAgg) {
    long long total4 = (long long)N * (D / 4);
    long long stride = (long long)gridDim.x * blockDim.x;
    float4 z = make_float4(0.f, 0.f, 0.f, 0.f);
    for (long long i = blockIdx.x * (long long)blockDim.x + threadIdx.x;
         i < total4; i += stride) {
        int row = (int)(i >> 5);
        float inv = g_deg[row];
        float4 a = ((const float4*)g_agg)[i];
        float4 o = ((float4*)outb)[i];
        o.x += a.x * inv; o.y += a.y * inv;
        o.z += a.z * inv; o.w += a.w * inv;
        if (doRelu) {
            o.x = fmaxf(o.x, 0.f); o.y = fmaxf(o.y, 0.f);
            o.z = fmaxf(o.z, 0.f); o.w = fmaxf(o.w, 0.f);
        }
        ((float4*)outb)[i] = o;
        if (resetAgg) ((float4*)g_agg)[i] = z;
    }
}

// ---------------- launch ------------------------------------------------------
extern "C" void kernel_launch(void* const* d_in, const int* in_sizes, int n_in,
                              void* d_out, int out_size) {
    const float* x    = (const float*)d_in[0];
    const void*  edge = d_in[1];
    const float* Wl1  = (const float*)d_in[2];
    const float* Wr1  = (const float*)d_in[3];
    const float* b1   = (const float*)d_in[4];
    const float* Wl2  = (const float*)d_in[5];
    const float* Wr2  = (const float*)d_in[6];
    const float* b2   = (const float*)d_in[7];
    float* out = (float*)d_out;

    const int N = in_sizes[0] / D;
    const int E = in_sizes[1] / 2;
    const int tiles = (N + 127) / 128;

    float *xl, *h;
    uint4 *ah, *al, *wh, *wl;
    cudaGetSymbolAddress((void**)&xl, g_xl);
    cudaGetSymbolAddress((void**)&h,  g_h);
    cudaGetSymbolAddress((void**)&ah, g_ah);
    cudaGetSymbolAddress((void**)&al, g_al);
    cudaGetSymbolAddress((void**)&wh, g_wh);
    cudaGetSymbolAddress((void**)&wl, g_wl);

    const size_t shmem = SMEM_B32 * 4;   // 208896 bytes
    cudaFuncSetAttribute(gemm_tc_kernel,
                         cudaFuncAttributeMaxDynamicSharedMemorySize, (int)shmem);

    probe_idx_kernel<<<1, 32>>>(edge);
    zero_kernel<<<2048, 256>>>(N);
    deg_kernel<<<2048, 256>>>(edge, E);
    invdeg_kernel<<<(N + 255) / 256, 256>>>(N);

    // weight conversion: [Wl;Wr] stacked per layer, 128 rows each (2048 uint4)
    conv_kernel<<<8, 256>>>(Wl1, 128, 2048, wh + 0,    wl + 0);
    conv_kernel<<<8, 256>>>(Wr1, 128, 2048, wh + 2048, wl + 2048);
    conv_kernel<<<8, 256>>>(Wl2, 128, 2048, wh + 4096, wl + 4096);
    conv_kernel<<<8, 256>>>(Wr2, 128, 2048, wh + 6144, wl + 6144);

    // ---- layer 1 ----
    conv_kernel<<<2048, 256>>>(x, N, (long long)tiles * 2048, ah, al);
    gemm_tc_kernel<<<tiles, 512, shmem>>>(wh, wl, b1, xl, h, N);
    scatter_kernel<<<4096, 256>>>(edge, E);
    combine_kernel<<<2048, 256>>>(h, N, /*relu=*/1, /*reset=*/1);

    // ---- layer 2 ----
    conv_kernel<<<2048, 256>>>(h, N, (long long)tiles * 2048, ah, al);
    gemm_tc_kernel<<<tiles, 512, shmem>>>(wh + 4096, wl + 4096, b2, xl, out, N);
    scatter_kernel<<<4096, 256>>>(edge, E);
    combine_kernel<<<2048, 256>>>(out, N, /*relu=*/0, /*reset=*/0);
}

// round 4
// speedup vs baseline: 1.7849x; 1.4098x over previous
#include <cuda_runtime.h>
#include <cuda_bf16.h>
#include <cstdint>

#define D 128
#define MAXN 100000
#define MAXE 1600000
#define MAXTILES ((MAXN + 127) / 128)   // 782

// ---------------- scratch (device globals; no allocations allowed) ----------
__device__ float g_inv [MAXN];                     // 1/max(deg,1)
__device__ int   g_cnt [MAXN];                     // degree histogram
__device__ int   g_off [MAXN + 1];                 // CSR offsets
__device__ int   g_cur [MAXN];                     // fill cursors
__device__ int   g_csr [MAXE];                     // src indices bucketed by dst
__device__ float g_xl  [(size_t)MAXN * D];         // A @ Wl^T   (messages)
__device__ float g_self[(size_t)MAXN * D];         // A @ Wr^T + b (self path)
__device__ int   g_is64;
// bf16 hi/lo staging, row-major [row][128] bf16 (16 uint4 per row)
__device__ uint4 g_ah[(size_t)MAXTILES * 2048];
__device__ uint4 g_al[(size_t)MAXTILES * 2048];
__device__ uint4 g_wh[2 * 4096];   // per layer: [Wl;Wr] stacked = 256 rows
__device__ uint4 g_wl[2 * 4096];

// ---------------- small helpers ---------------------------------------------
__device__ __forceinline__ int load_idx(const void* p, int is64, long long i) {
    if (is64) return (int)((const long long*)p)[i];
    return ((const int*)p)[i];
}

__global__ void probe_idx_kernel(const void* idx) {
    if (threadIdx.x == 0 && blockIdx.x == 0) {
        const unsigned int* w = (const unsigned int*)idx;
        int all0 = 1;
        for (int i = 0; i < 128; i++)
            if (w[2 * i + 1] != 0u) { all0 = 0; break; }
        g_is64 = all0;
    }
}

__global__ void zero_cnt_kernel(int N) {
    int i = blockIdx.x * blockDim.x + threadIdx.x;
    if (i < N) g_cnt[i] = 0;
}

__global__ void deg_kernel(const void* __restrict__ edge, int E) {
    int is64 = g_is64;
    long long stride = (long long)gridDim.x * blockDim.x;
    for (long long e = blockIdx.x * (long long)blockDim.x + threadIdx.x;
         e < E; e += stride) {
        int d = load_idx(edge, is64, (long long)E + e);
        atomicAdd(&g_cnt[d], 1);
    }
}

__global__ void invdeg_kernel(int N) {
    int i = blockIdx.x * blockDim.x + threadIdx.x;
    if (i < N) g_inv[i] = 1.0f / fmaxf((float)g_cnt[i], 1.0f);
}

// ---- 3-stage exclusive scan of g_cnt -> g_off (+g_cur), off[N]=E ------------
__device__ int g_bsum[512];

__global__ void scan1_kernel(int N) {
    __shared__ int sh[256];
    int i = blockIdx.x * 256 + threadIdx.x;
    sh[threadIdx.x] = (i < N) ? g_cnt[i] : 0;
    __syncthreads();
#pragma unroll
    for (int s = 128; s > 0; s >>= 1) {
        if (threadIdx.x < s) sh[threadIdx.x] += sh[threadIdx.x + s];
        __syncthreads();
    }
    if (threadIdx.x == 0) g_bsum[blockIdx.x] = sh[0];
}

__global__ void scan2_kernel(int nb) {
    if (threadIdx.x == 0) {
        int acc = 0;
        for (int i = 0; i < nb; i++) { int v = g_bsum[i]; g_bsum[i] = acc; acc += v; }
    }
}

__global__ void scan3_kernel(int N, int E) {
    __shared__ int sh[256];
    int i = blockIdx.x * 256 + threadIdx.x;
    int v = (i < N) ? g_cnt[i] : 0;
    sh[threadIdx.x] = v;
    __syncthreads();
#pragma unroll
    for (int s = 1; s < 256; s <<= 1) {
        int t = (threadIdx.x >= s) ? sh[threadIdx.x - s] : 0;
        __syncthreads();
        sh[threadIdx.x] += t;
        __syncthreads();
    }
    if (i < N) {
        int excl = g_bsum[blockIdx.x] + sh[threadIdx.x] - v;
        g_off[i] = excl;
        g_cur[i] = excl;
    }
    if (i == N - 1) g_off[N] = E;
}

__global__ void build_csr_kernel(const void* __restrict__ edge, int E) {
    int is64 = g_is64;
    long long stride = (long long)gridDim.x * blockDim.x;
    for (long long e = blockIdx.x * (long long)blockDim.x + threadIdx.x;
         e < E; e += stride) {
        int s = load_idx(edge, is64, e);
        int d = load_idx(edge, is64, (long long)E + e);
        int pos = atomicAdd(&g_cur[d], 1);
        g_csr[pos] = s;
    }
}

// ---------------- fp32 -> bf16 hi/lo, plain row-major ------------------------
__global__ void conv_kernel(const float* __restrict__ A, int Nrows,
                            long long totalChunks,
                            uint4* __restrict__ oh, uint4* __restrict__ ol) {
    long long stride = (long long)gridDim.x * blockDim.x;
    for (long long c = blockIdx.x * (long long)blockDim.x + threadIdx.x;
         c < totalChunks; c += stride) {
        int row = (int)(c >> 4);
        int kc  = (int)(c & 15);
        float v[8];
        if (row < Nrows) {
            const float4* ap = (const float4*)(A + (size_t)row * D + kc * 8);
            float4 a = ap[0], b = ap[1];
            v[0]=a.x; v[1]=a.y; v[2]=a.z; v[3]=a.w;
            v[4]=b.x; v[5]=b.y; v[6]=b.z; v[7]=b.w;
        } else {
#pragma unroll
            for (int i = 0; i < 8; i++) v[i] = 0.f;
        }
        unsigned int hw[4], lw[4];
#pragma unroll
        for (int i = 0; i < 4; i++) {
            float f0 = v[2*i], f1 = v[2*i+1];
            __nv_bfloat16 h0 = __float2bfloat16(f0);
            __nv_bfloat16 h1 = __float2bfloat16(f1);
            __nv_bfloat16 l0 = __float2bfloat16(f0 - __bfloat162float(h0));
            __nv_bfloat16 l1 = __float2bfloat16(f1 - __bfloat162float(h1));
            hw[i] = (unsigned int)__bfloat16_as_ushort(h0) |
                    ((unsigned int)__bfloat16_as_ushort(h1) << 16);
            lw[i] = (unsigned int)__bfloat16_as_ushort(l0) |
                    ((unsigned int)__bfloat16_as_ushort(l1) << 16);
        }
        oh[c] = make_uint4(hw[0], hw[1], hw[2], hw[3]);
        ol[c] = make_uint4(lw[0], lw[1], lw[2], lw[3]);
    }
}

// ---------------- mma.sync bf16 GEMM with ldmatrix --------------------------
// grid (tiles, 2): y=0 -> out0 = A@Wl^T ; y=1 -> out1 = A@Wr^T + bias
// 3-term fp32 emulation: ah@wh + ah@wl + al@wh
__device__ __forceinline__ void mma16816(float* acc, const unsigned* a,
                                         const unsigned* b) {
    asm volatile(
        "mma.sync.aligned.m16n8k16.row.col.f32.bf16.bf16.f32 "
        "{%0,%1,%2,%3}, {%4,%5,%6,%7}, {%8,%9}, {%0,%1,%2,%3};"
        : "+f"(acc[0]), "+f"(acc[1]), "+f"(acc[2]), "+f"(acc[3])
        : "r"(a[0]), "r"(a[1]), "r"(a[2]), "r"(a[3]), "r"(b[0]), "r"(b[1]));
}
__device__ __forceinline__ void ldsm4(unsigned* r, uint32_t a) {
    asm volatile("ldmatrix.sync.aligned.m8n8.x4.shared.b16 {%0,%1,%2,%3}, [%4];"
        : "=r"(r[0]), "=r"(r[1]), "=r"(r[2]), "=r"(r[3]) : "r"(a));
}
__device__ __forceinline__ uint32_t smem_u32(const void* p) {
    uint32_t a;
    asm("{ .reg .u64 t; cvta.to.shared.u64 t, %1; cvt.u32.u64 %0, t; }"
        : "=r"(a) : "l"(p));
    return a;
}

// SMEM row = 272B (17 uint4): ldmatrix 8-row phases hit banks 4r..4r+3 -> conflict-free
#define RS16 17
#define RSB  272
#define AH4  0
#define AL4  2176
#define WH4  4352
#define WL4  6528
#define SMEMB 139264

__global__ __launch_bounds__(512, 1)
void gemm_tc_kernel(const uint4* __restrict__ whL, const uint4* __restrict__ wlL,
                    const float* __restrict__ bias,
                    float* __restrict__ out0, float* __restrict__ out1, int N) {
    extern __shared__ uint4 smem4[];

    const int tid  = threadIdx.x;
    const int wid  = tid >> 5;
    const int lane = tid & 31;
    const int tile = blockIdx.x;
    const int osel = blockIdx.y;

    const int mrow = (wid & 3) * 32;
    const int ncol = (wid >> 2) * 32;

    // ---- stage A (hi/lo) and this output's W (hi/lo) ----
    {
        const uint4* ga = g_ah + (size_t)tile * 2048;
        const uint4* gl = g_al + (size_t)tile * 2048;
        const uint4* wh = whL + (size_t)osel * 2048;
        const uint4* wl = wlL + (size_t)osel * 2048;
#pragma unroll
        for (int i = tid; i < 2048; i += 512) {
            int r = i >> 4, c = i & 15;
            smem4[AH4 + r * RS16 + c] = ga[i];
            smem4[AL4 + r * RS16 + c] = gl[i];
            smem4[WH4 + r * RS16 + c] = wh[i];
            smem4[WL4 + r * RS16 + c] = wl[i];
        }
    }
    __syncthreads();

    const uint32_t sb = smem_u32(smem4);
    // A frag addresses (lane -> row lane&15, 16B col block lane>>4)
    const uint32_t aoff = (uint32_t)((mrow + (lane & 15)) * RSB + (lane >> 4) * 16);
    const uint32_t aH0 = sb + AH4 * 16 + aoff;
    const uint32_t aH1 = aH0 + 16 * RSB;
    const uint32_t aL0 = sb + AL4 * 16 + aoff;
    const uint32_t aL1 = aL0 + 16 * RSB;
    // W frag addresses: matrix sel m=lane>>3 : {nt0-klo, nt0-khi, nt1-klo, nt1-khi}
    const int msel = lane >> 3;
    const uint32_t woff = (uint32_t)((ncol + ((msel >> 1) * 8) + (lane & 7)) * RSB +
                                     (msel & 1) * 16);
    const uint32_t wH0 = sb + WH4 * 16 + woff;            // nt pair 0 (nt 0,1)
    const uint32_t wH1 = wH0 + 16 * RSB;                  // nt pair 1 (nt 2,3)
    const uint32_t wL0 = sb + WL4 * 16 + woff;
    const uint32_t wL1 = wL0 + 16 * RSB;

    float acc[2][4][4];
#pragma unroll
    for (int mt = 0; mt < 2; mt++)
#pragma unroll
        for (int nt = 0; nt < 4; nt++)
#pragma unroll
            for (int i = 0; i < 4; i++) acc[mt][nt][i] = 0.f;

#pragma unroll
    for (int kc = 0; kc < 8; kc++) {
        const uint32_t kb = kc * 32;
        unsigned ah[2][4], al[2][4], whf[2][4], wlf[2][4];
        ldsm4(ah[0], aH0 + kb); ldsm4(ah[1], aH1 + kb);
        ldsm4(al[0], aL0 + kb); ldsm4(al[1], aL1 + kb);
        ldsm4(whf[0], wH0 + kb); ldsm4(whf[1], wH1 + kb);
        ldsm4(wlf[0], wL0 + kb); ldsm4(wlf[1], wL1 + kb);
#pragma unroll
        for (int mt = 0; mt < 2; mt++)
#pragma unroll
            for (int nt = 0; nt < 4; nt++) {
                const unsigned* bh = &whf[nt >> 1][(nt & 1) * 2];
                const unsigned* bl = &wlf[nt >> 1][(nt & 1) * 2];
                mma16816(acc[mt][nt], ah[mt], bh);
                mma16816(acc[mt][nt], ah[mt], bl);
                mma16816(acc[mt][nt], al[mt], bh);
            }
    }

    // ---- store -------------------------------------------------------------
    float* outp = osel ? out1 : out0;
    const int q = lane & 3, g = lane >> 2;
#pragma unroll
    for (int nt = 0; nt < 4; nt++) {
        int col = ncol + nt * 8 + q * 2;
        float b0 = 0.f, b1 = 0.f;
        if (osel) { b0 = __ldg(bias + col); b1 = __ldg(bias + col + 1); }
#pragma unroll
        for (int mt = 0; mt < 2; mt++) {
            int r = tile * 128 + mrow + mt * 16 + g;
            if (r < N) {
                float2 v; v.x = acc[mt][nt][0] + b0; v.y = acc[mt][nt][1] + b1;
                *(float2*)(outp + (size_t)r * D + col) = v;
            }
            if (r + 8 < N) {
                float2 v; v.x = acc[mt][nt][2] + b0; v.y = acc[mt][nt][3] + b1;
                *(float2*)(outp + (size_t)(r + 8) * D + col) = v;
            }
        }
    }
}

// ---------------- CSR pull: out = [relu](self + mean_agg(xl)) ---------------
// warp per node; optional fp32 output and/or bf16 hi/lo output (GEMM staging)
__global__ void pull_kernel(const float* __restrict__ xl,
                            const float* __restrict__ self,
                            float* __restrict__ out32,
                            uint2* __restrict__ oh, uint2* __restrict__ ol,
                            int N, int Npad, int doRelu) {
    const int lane = threadIdx.x & 31;
    long long w  = (blockIdx.x * (long long)blockDim.x + threadIdx.x) >> 5;
    long long nw = ((long long)gridDim.x * blockDim.x) >> 5;

    for (long long node = w; node < Npad; node += nw) {
        if (node < N) {
            const int beg = g_off[node], end = g_off[node + 1];
            float4 acc = make_float4(0.f, 0.f, 0.f, 0.f);
            for (int e = beg; e < end; e++) {
                int s = __ldg(g_csr + e);
                float4 m = *(const float4*)(xl + (size_t)s * D + lane * 4);
                acc.x += m.x; acc.y += m.y; acc.z += m.z; acc.w += m.w;
            }
            float inv = g_inv[node];
            float4 sv = *(const float4*)(self + (size_t)node * D + lane * 4);
            float4 o;
            o.x = sv.x + acc.x * inv; o.y = sv.y + acc.y * inv;
            o.z = sv.z + acc.z * inv; o.w = sv.w + acc.w * inv;
            if (doRelu) {
                o.x = fmaxf(o.x, 0.f); o.y = fmaxf(o.y, 0.f);
                o.z = fmaxf(o.z, 0.f); o.w = fmaxf(o.w, 0.f);
            }
            if (out32)
                *(float4*)(out32 + (size_t)node * D + lane * 4) = o;
            if (oh) {
                float f[4] = {o.x, o.y, o.z, o.w};
                unsigned hw[4], lw[4];
#pragma unroll
                for (int i = 0; i < 4; i++) {
                    __nv_bfloat16 h = __float2bfloat16(f[i]);
                    __nv_bfloat16 l = __float2bfloat16(f[i] - __bfloat162float(h));
                    hw[i] = __bfloat16_as_ushort(h);
                    lw[i] = __bfloat16_as_ushort(l);
                }
                uint2 ph, pl;
                ph.x = hw[0] | (hw[1] << 16); ph.y = hw[2] | (hw[3] << 16);
                pl.x = lw[0] | (lw[1] << 16); pl.y = lw[2] | (lw[3] << 16);
                oh[(size_t)node * 32 + lane] = ph;
                ol[(size_t)node * 32 + lane] = pl;
            }
        } else if (oh) {
            uint2 z = make_uint2(0u, 0u);
            oh[(size_t)node * 32 + lane] = z;
            ol[(size_t)node * 32 + lane] = z;
        }
    }
}

// ---------------- launch ------------------------------------------------------
extern "C" void kernel_launch(void* const* d_in, const int* in_sizes, int n_in,
                              void* d_out, int out_size) {
    const float* x    = (const float*)d_in[0];
    const void*  edge = d_in[1];
    const float* Wl1  = (const float*)d_in[2];
    const float* Wr1  = (const float*)d_in[3];
    const float* b1   = (const float*)d_in[4];
    const float* Wl2  = (const float*)d_in[5];
    const float* Wr2  = (const float*)d_in[6];
    const float* b2   = (const float*)d_in[7];
    float* out = (float*)d_out;

    const int N = in_sizes[0] / D;
    const int E = in_sizes[1] / 2;
    const int tiles = (N + 127) / 128;
    const int Npad = tiles * 128;
    const int scanBlocks = (N + 255) / 256;

    float *xl, *self;
    uint4 *ah, *al, *wh, *wl;
    cudaGetSymbolAddress((void**)&xl,   g_xl);
    cudaGetSymbolAddress((void**)&self, g_self);
    cudaGetSymbolAddress((void**)&ah,   g_ah);
    cudaGetSymbolAddress((void**)&al,   g_al);
    cudaGetSymbolAddress((void**)&wh,   g_wh);
    cudaGetSymbolAddress((void**)&wl,   g_wl);

    cudaFuncSetAttribute(gemm_tc_kernel,
                         cudaFuncAttributeMaxDynamicSharedMemorySize, SMEMB);

    // ---- graph preprocessing (per call) ----
    probe_idx_kernel<<<1, 32>>>(edge);
    zero_cnt_kernel<<<scanBlocks, 256>>>(N);
    deg_kernel<<<2048, 256>>>(edge, E);
    invdeg_kernel<<<scanBlocks, 256>>>(N);
    scan1_kernel<<<scanBlocks, 256>>>(N);
    scan2_kernel<<<1, 32>>>(scanBlocks);
    scan3_kernel<<<scanBlocks, 256>>>(N, E);
    build_csr_kernel<<<2048, 256>>>(edge, E);

    // ---- weight conversion: [Wl;Wr] stacked per layer ----
    conv_kernel<<<8, 256>>>(Wl1, 128, 2048, wh + 0,    wl + 0);
    conv_kernel<<<8, 256>>>(Wr1, 128, 2048, wh + 2048, wl + 2048);
    conv_kernel<<<8, 256>>>(Wl2, 128, 2048, wh + 4096, wl + 4096);
    conv_kernel<<<8, 256>>>(Wr2, 128, 2048, wh + 6144, wl + 6144);

    dim3 ggrid(tiles, 2);

    // ---- layer 1 ----
    conv_kernel<<<2048, 256>>>(x, N, (long long)tiles * 2048, ah, al);
    gemm_tc_kernel<<<ggrid, 512, SMEMB>>>(wh, wl, b1, xl, self, N);
    // h = relu(self + mean) -> written directly as bf16 hi/lo GEMM staging
    pull_kernel<<<tiles * 16, 256>>>(xl, self, nullptr,
                                     (uint2*)ah, (uint2*)al, N, Npad, 1);

    // ---- layer 2 ----
    gemm_tc_kernel<<<ggrid, 512, SMEMB>>>(wh + 4096, wl + 4096, b2, xl, self, N);
    pull_kernel<<<tiles * 16, 256>>>(xl, self, out,
                                     nullptr, nullptr, N, Npad, 0);
}

// round 5
// speedup vs baseline: 2.5676x; 1.4385x over previous
#include <cuda_runtime.h>
#include <cuda_fp16.h>
#include <cstdint>

#define D 128
#define MAXN 100000
#define MAXE 1600000
#define MAXTILES ((MAXN + 127) / 128)   // 782

// ---------------- scratch (device globals; no allocations allowed) ----------
__device__ float g_inv [MAXN];                     // 1/max(deg,1)
__device__ int   g_cnt [MAXN];                     // degree histogram
__device__ int   g_off [MAXN + 1];                 // CSR offsets
__device__ int   g_cur [MAXN];                     // fill cursors
__device__ int   g_csr [MAXE];                     // src indices bucketed by dst
__device__ float g_self[(size_t)MAXN * D];         // A @ Wr^T + b (self path)
__device__ uint2 g_xl16[(size_t)MAXN * 32];        // messages A@Wl^T, fp16 rows
__device__ int   g_is64;
// fp16 staging, row-major [row][128] fp16 (16 uint4 per row)
__device__ uint4 g_x16[(size_t)MAXTILES * 2048];   // GEMM A input
__device__ uint4 g_wh[2 * 4096];   // per layer: [Wl;Wr] stacked = 256 rows, fp16 hi
__device__ uint4 g_wl[2 * 4096];   // fp16 lo
__device__ int   g_bsum[512];

// ---------------- small helpers ---------------------------------------------
__device__ __forceinline__ int load_idx(const void* p, int is64, long long i) {
    if (is64) return (int)((const long long*)p)[i];
    return ((const int*)p)[i];
}

// probe edge dtype + zero degree histogram
__global__ void prep_kernel(const void* idx, int N) {
    int i = blockIdx.x * blockDim.x + threadIdx.x;
    if (i < N) g_cnt[i] = 0;
    if (i == 0) {
        const unsigned int* w = (const unsigned int*)idx;
        int all0 = 1;
        for (int k = 0; k < 128; k++)
            if (w[2 * k + 1] != 0u) { all0 = 0; break; }
        g_is64 = all0;
    }
}

__global__ void deg_kernel(const void* __restrict__ edge, int E) {
    int is64 = g_is64;
    long long stride = (long long)gridDim.x * blockDim.x;
    for (long long e = blockIdx.x * (long long)blockDim.x + threadIdx.x;
         e < E; e += stride) {
        int d = load_idx(edge, is64, (long long)E + e);
        atomicAdd(&g_cnt[d], 1);
    }
}

// ---- 3-stage exclusive scan of g_cnt -> g_off (+g_cur, g_inv) --------------
__global__ void scan1_kernel(int N) {
    __shared__ int sh[256];
    int i = blockIdx.x * 256 + threadIdx.x;
    sh[threadIdx.x] = (i < N) ? g_cnt[i] : 0;
    __syncthreads();
#pragma unroll
    for (int s = 128; s > 0; s >>= 1) {
        if (threadIdx.x < s) sh[threadIdx.x] += sh[threadIdx.x + s];
        __syncthreads();
    }
    if (threadIdx.x == 0) g_bsum[blockIdx.x] = sh[0];
}

__global__ void scan2_kernel(int nb) {
    if (threadIdx.x == 0) {
        int acc = 0;
        for (int i = 0; i < nb; i++) { int v = g_bsum[i]; g_bsum[i] = acc; acc += v; }
    }
}

__global__ void scan3_kernel(int N, int E) {
    __shared__ int sh[256];
    int i = blockIdx.x * 256 + threadIdx.x;
    int v = (i < N) ? g_cnt[i] : 0;
    sh[threadIdx.x] = v;
    __syncthreads();
#pragma unroll
    for (int s = 1; s < 256; s <<= 1) {
        int t = (threadIdx.x >= s) ? sh[threadIdx.x - s] : 0;
        __syncthreads();
        sh[threadIdx.x] += t;
        __syncthreads();
    }
    if (i < N) {
        int excl = g_bsum[blockIdx.x] + sh[threadIdx.x] - v;
        g_off[i] = excl;
        g_cur[i] = excl;
        g_inv[i] = 1.0f / fmaxf((float)v, 1.0f);
    }
    if (i == N - 1) g_off[N] = E;
}

__global__ void build_csr_kernel(const void* __restrict__ edge, int E) {
    int is64 = g_is64;
    long long stride = (long long)gridDim.x * blockDim.x;
    for (long long e = blockIdx.x * (long long)blockDim.x + threadIdx.x;
         e < E; e += stride) {
        int s = load_idx(edge, is64, e);
        int d = load_idx(edge, is64, (long long)E + e);
        int pos = atomicAdd(&g_cur[d], 1);
        g_csr[pos] = s;
    }
}

// ---------------- weight conversion: fp32 -> fp16 hi/lo ---------------------
// 4 weight matrices (Wl1,Wr1,Wl2,Wr2), each 128x128, into stacked layout:
// layer L rows [0,128)=Wl, [128,256)=Wr at g_wh/g_wl + L*4096
__global__ void conv_w_kernel(const float* __restrict__ W0, const float* __restrict__ W1,
                              const float* __restrict__ W2, const float* __restrict__ W3) {
    int c = blockIdx.x * blockDim.x + threadIdx.x;   // 0 .. 4*2048-1
    if (c >= 4 * 2048) return;
    int which = c >> 11;
    int local = c & 2047;
    int row = local >> 4, kc = local & 15;
    const float* W = (which == 0) ? W0 : (which == 1) ? W1 : (which == 2) ? W2 : W3;
    const float4* ap = (const float4*)(W + (size_t)row * D + kc * 8);
    float4 a = ap[0], b = ap[1];
    float v[8] = {a.x, a.y, a.z, a.w, b.x, b.y, b.z, b.w};
    unsigned hw[4], lw[4];
#pragma unroll
    for (int i = 0; i < 4; i++) {
        __half h0 = __float2half_rn(v[2*i]);
        __half h1 = __float2half_rn(v[2*i+1]);
        __half l0 = __float2half_rn(v[2*i] - __half2float(h0));
        __half l1 = __float2half_rn(v[2*i+1] - __half2float(h1));
        hw[i] = (unsigned)__half_as_ushort(h0) | ((unsigned)__half_as_ushort(h1) << 16);
        lw[i] = (unsigned)__half_as_ushort(l0) | ((unsigned)__half_as_ushort(l1) << 16);
    }
    // which: 0->layer0 rows 0-127, 1->layer0 rows 128-255, 2->layer1 rows 0-127, 3->layer1 rows 128-255
    int layer = which >> 1, half = which & 1;
    long long o = (long long)layer * 4096 + half * 2048 + local;
    g_wh[o] = make_uint4(hw[0], hw[1], hw[2], hw[3]);
    g_wl[o] = make_uint4(lw[0], lw[1], lw[2], lw[3]);
}

// ---------------- x: fp32 -> fp16, row-major ---------------------------------
__global__ void conv_x_kernel(const float* __restrict__ A, int Nrows,
                              long long totalChunks) {
    long long stride = (long long)gridDim.x * blockDim.x;
    for (long long c = blockIdx.x * (long long)blockDim.x + threadIdx.x;
         c < totalChunks; c += stride) {
        int row = (int)(c >> 4);
        int kc  = (int)(c & 15);
        unsigned w[4] = {0u, 0u, 0u, 0u};
        if (row < Nrows) {
            const float4* ap = (const float4*)(A + (size_t)row * D + kc * 8);
            float4 a = ap[0], b = ap[1];
            float v[8] = {a.x, a.y, a.z, a.w, b.x, b.y, b.z, b.w};
#pragma unroll
            for (int i = 0; i < 4; i++) {
                __half h0 = __float2half_rn(v[2*i]);
                __half h1 = __float2half_rn(v[2*i+1]);
                w[i] = (unsigned)__half_as_ushort(h0) |
                       ((unsigned)__half_as_ushort(h1) << 16);
            }
        }
        g_x16[c] = make_uint4(w[0], w[1], w[2], w[3]);
    }
}

// ---------------- mma.sync fp16 GEMM with ldmatrix ---------------------------
// grid (tiles, 2): y=0 -> xl16 = fp16(A@Wl^T) ; y=1 -> self = A@Wr^T + bias (fp32)
// 2-term: a @ wh + a @ wl   (W split fp16 hi/lo; activation already fp16)
__device__ __forceinline__ void mma16816(float* acc, const unsigned* a,
                                         const unsigned* b) {
    asm volatile(
        "mma.sync.aligned.m16n8k16.row.col.f32.f16.f16.f32 "
        "{%0,%1,%2,%3}, {%4,%5,%6,%7}, {%8,%9}, {%0,%1,%2,%3};"
        : "+f"(acc[0]), "+f"(acc[1]), "+f"(acc[2]), "+f"(acc[3])
        : "r"(a[0]), "r"(a[1]), "r"(a[2]), "r"(a[3]), "r"(b[0]), "r"(b[1]));
}
__device__ __forceinline__ void ldsm4(unsigned* r, uint32_t a) {
    asm volatile("ldmatrix.sync.aligned.m8n8.x4.shared.b16 {%0,%1,%2,%3}, [%4];"
        : "=r"(r[0]), "=r"(r[1]), "=r"(r[2]), "=r"(r[3]) : "r"(a));
}
__device__ __forceinline__ uint32_t smem_u32(const void* p) {
    uint32_t a;
    asm("{ .reg .u64 t; cvta.to.shared.u64 t, %1; cvt.u32.u64 %0, t; }"
        : "=r"(a) : "l"(p));
    return a;
}

// SMEM row = 272B (17 uint4): ldmatrix 8-row phases -> conflict-free
#define RS16 17
#define RSB  272
#define A4   0
#define WH4  2176
#define WL4  4352
#define SMEMB 104448

__global__ __launch_bounds__(512, 1)
void gemm_tc_kernel(const float* __restrict__ bias, int layer,
                    float* __restrict__ selfp, int N) {
    extern __shared__ uint4 smem4[];

    const int tid  = threadIdx.x;
    const int wid  = tid >> 5;
    const int lane = tid & 31;
    const int tile = blockIdx.x;
    const int osel = blockIdx.y;

    const int mrow = (wid & 3) * 32;
    const int ncol = (wid >> 2) * 32;

    // ---- stage A and this output's W (hi/lo) ----
    {
        const uint4* ga = g_x16 + (size_t)tile * 2048;
        const uint4* wh = g_wh + (size_t)layer * 4096 + (size_t)osel * 2048;
        const uint4* wl = g_wl + (size_t)layer * 4096 + (size_t)osel * 2048;
#pragma unroll
        for (int i = tid; i < 2048; i += 512) {
            int r = i >> 4, c = i & 15;
            smem4[A4  + r * RS16 + c] = ga[i];
            smem4[WH4 + r * RS16 + c] = wh[i];
            smem4[WL4 + r * RS16 + c] = wl[i];
        }
    }
    __syncthreads();

    const uint32_t sb = smem_u32(smem4);
    const uint32_t aoff = (uint32_t)((mrow + (lane & 15)) * RSB + (lane >> 4) * 16);
    const uint32_t a0 = sb + A4 * 16 + aoff;
    const uint32_t a1 = a0 + 16 * RSB;
    const int msel = lane >> 3;
    const uint32_t woff = (uint32_t)((ncol + ((msel >> 1) * 8) + (lane & 7)) * RSB +
                                     (msel & 1) * 16);
    const uint32_t wH0 = sb + WH4 * 16 + woff;
    const uint32_t wH1 = wH0 + 16 * RSB;
    const uint32_t wL0 = sb + WL4 * 16 + woff;
    const uint32_t wL1 = wL0 + 16 * RSB;

    float acc[2][4][4];
#pragma unroll
    for (int mt = 0; mt < 2; mt++)
#pragma unroll
        for (int nt = 0; nt < 4; nt++)
#pragma unroll
            for (int i = 0; i < 4; i++) acc[mt][nt][i] = 0.f;

#pragma unroll
    for (int kc = 0; kc < 8; kc++) {
        const uint32_t kb = kc * 32;
        unsigned af[2][4], whf[2][4], wlf[2][4];
        ldsm4(af[0], a0 + kb); ldsm4(af[1], a1 + kb);
        ldsm4(whf[0], wH0 + kb); ldsm4(whf[1], wH1 + kb);
        ldsm4(wlf[0], wL0 + kb); ldsm4(wlf[1], wL1 + kb);
#pragma unroll
        for (int mt = 0; mt < 2; mt++)
#pragma unroll
            for (int nt = 0; nt < 4; nt++) {
                const unsigned* bh = &whf[nt >> 1][(nt & 1) * 2];
                const unsigned* bl = &wlf[nt >> 1][(nt & 1) * 2];
                mma16816(acc[mt][nt], af[mt], bh);
                mma16816(acc[mt][nt], af[mt], bl);
            }
    }

    // ---- store -------------------------------------------------------------
    const int q = lane & 3, g = lane >> 2;
    if (osel == 0) {
        __half* xp = (__half*)g_xl16;
#pragma unroll
        for (int nt = 0; nt < 4; nt++) {
            int col = ncol + nt * 8 + q * 2;
#pragma unroll
            for (int mt = 0; mt < 2; mt++) {
                int r = tile * 128 + mrow + mt * 16 + g;
                if (r < N)
                    *(__half2*)(xp + (size_t)r * D + col) =
                        __floats2half2_rn(acc[mt][nt][0], acc[mt][nt][1]);
                if (r + 8 < N)
                    *(__half2*)(xp + (size_t)(r + 8) * D + col) =
                        __floats2half2_rn(acc[mt][nt][2], acc[mt][nt][3]);
            }
        }
    } else {
#pragma unroll
        for (int nt = 0; nt < 4; nt++) {
            int col = ncol + nt * 8 + q * 2;
            float b0 = __ldg(bias + col), b1 = __ldg(bias + col + 1);
#pragma unroll
            for (int mt = 0; mt < 2; mt++) {
                int r = tile * 128 + mrow + mt * 16 + g;
                if (r < N) {
                    float2 v; v.x = acc[mt][nt][0] + b0; v.y = acc[mt][nt][1] + b1;
                    *(float2*)(selfp + (size_t)r * D + col) = v;
                }
                if (r + 8 < N) {
                    float2 v; v.x = acc[mt][nt][2] + b0; v.y = acc[mt][nt][3] + b1;
                    *(float2*)(selfp + (size_t)(r + 8) * D + col) = v;
                }
            }
        }
    }
}

// ---------------- CSR pull: out = [relu](self + mean_agg(xl16)) -------------
// warp per node; fp16 gather, fp32 accumulate
__global__ void pull_kernel(float* __restrict__ out32, int writeStage,
                            int N, int Npad, int doRelu) {
    const int lane = threadIdx.x & 31;
    long long w  = (blockIdx.x * (long long)blockDim.x + threadIdx.x) >> 5;
    long long nw = ((long long)gridDim.x * blockDim.x) >> 5;

    uint2* stage = (uint2*)g_x16;

    for (long long node = w; node < Npad; node += nw) {
        if (node < N) {
            const int beg = g_off[node], end = g_off[node + 1];
            float4 acc = make_float4(0.f, 0.f, 0.f, 0.f);
            for (int e = beg; e < end; e++) {
                int s = __ldg(g_csr + e);
                uint2 m = g_xl16[(size_t)s * 32 + lane];
                float2 f0 = __half22float2(*(__half2*)&m.x);
                float2 f1 = __half22float2(*(__half2*)&m.y);
                acc.x += f0.x; acc.y += f0.y; acc.z += f1.x; acc.w += f1.y;
            }
            float inv = g_inv[node];
            float4 sv = *(const float4*)(g_self + (size_t)node * D + lane * 4);
            float4 o;
            o.x = sv.x + acc.x * inv; o.y = sv.y + acc.y * inv;
            o.z = sv.z + acc.z * inv; o.w = sv.w + acc.w * inv;
            if (doRelu) {
                o.x = fmaxf(o.x, 0.f); o.y = fmaxf(o.y, 0.f);
                o.z = fmaxf(o.z, 0.f); o.w = fmaxf(o.w, 0.f);
            }
            if (out32)
                *(float4*)(out32 + (size_t)node * D + lane * 4) = o;
            if (writeStage) {
                uint2 p;
                __half2 h0 = __floats2half2_rn(o.x, o.y);
                __half2 h1 = __floats2half2_rn(o.z, o.w);
                p.x = *(unsigned*)&h0; p.y = *(unsigned*)&h1;
                stage[(size_t)node * 32 + lane] = p;
            }
        } else if (writeStage) {
            stage[(size_t)node * 32 + lane] = make_uint2(0u, 0u);
        }
    }
}

// ---------------- launch ------------------------------------------------------
extern "C" void kernel_launch(void* const* d_in, const int* in_sizes, int n_in,
                              void* d_out, int out_size) {
    const float* x    = (const float*)d_in[0];
    const void*  edge = d_in[1];
    const float* Wl1  = (const float*)d_in[2];
    const float* Wr1  = (const float*)d_in[3];
    const float* b1   = (const float*)d_in[4];
    const float* Wl2  = (const float*)d_in[5];
    const float* Wr2  = (const float*)d_in[6];
    const float* b2   = (const float*)d_in[7];
    float* out = (float*)d_out;

    const int N = in_sizes[0] / D;
    const int E = in_sizes[1] / 2;
    const int tiles = (N + 127) / 128;
    const int Npad = tiles * 128;
    const int scanBlocks = (N + 255) / 256;

    float* self;
    cudaGetSymbolAddress((void**)&self, g_self);

    cudaFuncSetAttribute(gemm_tc_kernel,
                         cudaFuncAttributeMaxDynamicSharedMemorySize, SMEMB);

    // ---- graph preprocessing ----
    prep_kernel<<<scanBlocks, 256>>>(edge, N);
    deg_kernel<<<2048, 256>>>(edge, E);
    scan1_kernel<<<scanBlocks, 256>>>(N);
    scan2_kernel<<<1, 32>>>(scanBlocks);
    scan3_kernel<<<scanBlocks, 256>>>(N, E);
    build_csr_kernel<<<2048, 256>>>(edge, E);

    // ---- weight + input conversion ----
    conv_w_kernel<<<32, 256>>>(Wl1, Wr1, Wl2, Wr2);
    conv_x_kernel<<<2048, 256>>>(x, N, (long long)tiles * 2048);

    dim3 ggrid(tiles, 2);

    // ---- layer 1 ----
    gemm_tc_kernel<<<ggrid, 512, SMEMB>>>(b1, 0, self, N);
    pull_kernel<<<tiles * 16, 256>>>(nullptr, /*stage=*/1, N, Npad, /*relu=*/1);

    // ---- layer 2 ----
    gemm_tc_kernel<<<ggrid, 512, SMEMB>>>(b2, 1, self, N);
    pull_kernel<<<tiles * 16, 256>>>(out, /*stage=*/0, N, Npad, /*relu=*/0);
}

// round 6
// speedup vs baseline: 2.7703x; 1.0789x over previous
#include <cuda_runtime.h>
#include <cuda_fp16.h>
#include <cstdint>

#define D 128
#define MAXN 100000
#define MAXE 1600000
#define MAXTILES ((MAXN + 127) / 128)   // 782

// ---------------- scratch (device globals; no allocations allowed) ----------
__device__ float g_inv [MAXN];                     // 1/max(deg,1)
__device__ int   g_cnt [MAXN];                     // degree histogram
__device__ int   g_off [MAXN + 1];                 // CSR offsets
__device__ int   g_cur [MAXN];                     // fill cursors
__device__ int   g_csr [MAXE];                     // src indices bucketed by dst
__device__ float g_self[(size_t)MAXN * D];         // A @ Wr^T + b (self path)
__device__ uint2 g_xl16[(size_t)MAXN * 32];        // messages A@Wl^T, fp16 rows
__device__ int   g_is64;
// fp16 staging, row-major [row][128] fp16 (16 uint4 per row) — layer-2 GEMM input
__device__ uint4 g_x16[(size_t)MAXTILES * 2048];
__device__ uint4 g_wh[2 * 4096];   // per layer: [Wl;Wr] stacked = 256 rows, fp16 hi
__device__ uint4 g_wl[2 * 4096];   // fp16 lo
__device__ int   g_bsum[512];

// ---------------- small helpers ---------------------------------------------
__device__ __forceinline__ int load_idx(const void* p, int is64, long long i) {
    if (is64) return (int)((const long long*)p)[i];
    return ((const int*)p)[i];
}

// probe edge dtype + zero degree histogram
__global__ void prep_kernel(const void* idx, int N) {
    int i = blockIdx.x * blockDim.x + threadIdx.x;
    if (i < N) g_cnt[i] = 0;
    if (i == 0) {
        const unsigned int* w = (const unsigned int*)idx;
        int all0 = 1;
        for (int k = 0; k < 128; k++)
            if (w[2 * k + 1] != 0u) { all0 = 0; break; }
        g_is64 = all0;
    }
}

__global__ void deg_kernel(const void* __restrict__ edge, int E) {
    int is64 = g_is64;
    long long stride = (long long)gridDim.x * blockDim.x;
    for (long long e = blockIdx.x * (long long)blockDim.x + threadIdx.x;
         e < E; e += stride) {
        int d = load_idx(edge, is64, (long long)E + e);
        atomicAdd(&g_cnt[d], 1);
    }
}

// ---- 3-stage exclusive scan of g_cnt -> g_off (+g_cur, g_inv) --------------
__global__ void scan1_kernel(int N) {
    __shared__ int sh[256];
    int i = blockIdx.x * 256 + threadIdx.x;
    sh[threadIdx.x] = (i < N) ? g_cnt[i] : 0;
    __syncthreads();
#pragma unroll
    for (int s = 128; s > 0; s >>= 1) {
        if (threadIdx.x < s) sh[threadIdx.x] += sh[threadIdx.x + s];
        __syncthreads();
    }
    if (threadIdx.x == 0) g_bsum[blockIdx.x] = sh[0];
}

// parallel exclusive scan of g_bsum[0..nb) — one 512-thread block
__global__ void scan2_kernel(int nb) {
    __shared__ int sh[512];
    int t = threadIdx.x;
    int v = (t < nb) ? g_bsum[t] : 0;
    sh[t] = v;
    __syncthreads();
#pragma unroll
    for (int s = 1; s < 512; s <<= 1) {
        int u = (t >= s) ? sh[t - s] : 0;
        __syncthreads();
        sh[t] += u;
        __syncthreads();
    }
    if (t < nb) g_bsum[t] = sh[t] - v;   // exclusive
}

__global__ void scan3_kernel(int N, int E) {
    __shared__ int sh[256];
    int i = blockIdx.x * 256 + threadIdx.x;
    int v = (i < N) ? g_cnt[i] : 0;
    sh[threadIdx.x] = v;
    __syncthreads();
#pragma unroll
    for (int s = 1; s < 256; s <<= 1) {
        int t = (threadIdx.x >= s) ? sh[threadIdx.x - s] : 0;
        __syncthreads();
        sh[threadIdx.x] += t;
        __syncthreads();
    }
    if (i < N) {
        int excl = g_bsum[blockIdx.x] + sh[threadIdx.x] - v;
        g_off[i] = excl;
        g_cur[i] = excl;
        g_inv[i] = 1.0f / fmaxf((float)v, 1.0f);
    }
    if (i == N - 1) g_off[N] = E;
}

__global__ void build_csr_kernel(const void* __restrict__ edge, int E) {
    int is64 = g_is64;
    long long stride = (long long)gridDim.x * blockDim.x;
    for (long long e = blockIdx.x * (long long)blockDim.x + threadIdx.x;
         e < E; e += stride) {
        int s = load_idx(edge, is64, e);
        int d = load_idx(edge, is64, (long long)E + e);
        int pos = atomicAdd(&g_cur[d], 1);
        g_csr[pos] = s;
    }
}

// ---------------- weight conversion: fp32 -> fp16 hi/lo ---------------------
__global__ void conv_w_kernel(const float* __restrict__ W0, const float* __restrict__ W1,
                              const float* __restrict__ W2, const float* __restrict__ W3) {
    int c = blockIdx.x * blockDim.x + threadIdx.x;   // 0 .. 4*2048-1
    if (c >= 4 * 2048) return;
    int which = c >> 11;
    int local = c & 2047;
    int row = local >> 4, kc = local & 15;
    const float* W = (which == 0) ? W0 : (which == 1) ? W1 : (which == 2) ? W2 : W3;
    const float4* ap = (const float4*)(W + (size_t)row * D + kc * 8);
    float4 a = ap[0], b = ap[1];
    float v[8] = {a.x, a.y, a.z, a.w, b.x, b.y, b.z, b.w};
    unsigned hw[4], lw[4];
#pragma unroll
    for (int i = 0; i < 4; i++) {
        __half h0 = __float2half_rn(v[2*i]);
        __half h1 = __float2half_rn(v[2*i+1]);
        __half l0 = __float2half_rn(v[2*i] - __half2float(h0));
        __half l1 = __float2half_rn(v[2*i+1] - __half2float(h1));
        hw[i] = (unsigned)__half_as_ushort(h0) | ((unsigned)__half_as_ushort(h1) << 16);
        lw[i] = (unsigned)__half_as_ushort(l0) | ((unsigned)__half_as_ushort(l1) << 16);
    }
    int layer = which >> 1, half = which & 1;
    long long o = (long long)layer * 4096 + half * 2048 + local;
    g_wh[o] = make_uint4(hw[0], hw[1], hw[2], hw[3]);
    g_wl[o] = make_uint4(lw[0], lw[1], lw[2], lw[3]);
}

// ---------------- mma.sync fp16 GEMM with ldmatrix ---------------------------
// grid (tiles, 2): y=0 -> xl16 = fp16(A@Wl^T) ; y=1 -> self = A@Wr^T + bias (fp32)
// A source: a32 (fp32, converted during staging) if non-null, else g_x16 (fp16)
__device__ __forceinline__ void mma16816(float* acc, const unsigned* a,
                                         const unsigned* b) {
    asm volatile(
        "mma.sync.aligned.m16n8k16.row.col.f32.f16.f16.f32 "
        "{%0,%1,%2,%3}, {%4,%5,%6,%7}, {%8,%9}, {%0,%1,%2,%3};"
        : "+f"(acc[0]), "+f"(acc[1]), "+f"(acc[2]), "+f"(acc[3])
        : "r"(a[0]), "r"(a[1]), "r"(a[2]), "r"(a[3]), "r"(b[0]), "r"(b[1]));
}
__device__ __forceinline__ void ldsm4(unsigned* r, uint32_t a) {
    asm volatile("ldmatrix.sync.aligned.m8n8.x4.shared.b16 {%0,%1,%2,%3}, [%4];"
        : "=r"(r[0]), "=r"(r[1]), "=r"(r[2]), "=r"(r[3]) : "r"(a));
}
__device__ __forceinline__ uint32_t smem_u32(const void* p) {
    uint32_t a;
    asm("{ .reg .u64 t; cvta.to.shared.u64 t, %1; cvt.u32.u64 %0, t; }"
        : "=r"(a) : "l"(p));
    return a;
}

// SMEM row = 272B (17 uint4): ldmatrix 8-row phases -> conflict-free
#define RS16 17
#define RSB  272
#define A4   0
#define WH4  2176
#define WL4  4352
#define SMEMB 104448

__global__ __launch_bounds__(512, 1)
void gemm_tc_kernel(const float* __restrict__ bias, int layer,
                    float* __restrict__ selfp, int N,
                    const float* __restrict__ a32) {
    extern __shared__ uint4 smem4[];

    const int tid  = threadIdx.x;
    const int wid  = tid >> 5;
    const int lane = tid & 31;
    const int tile = blockIdx.x;
    const int osel = blockIdx.y;

    const int mrow = (wid & 3) * 32;
    const int ncol = (wid >> 2) * 32;

    // ---- stage A and this output's W (hi/lo) ----
    {
        const uint4* wh = g_wh + (size_t)layer * 4096 + (size_t)osel * 2048;
        const uint4* wl = g_wl + (size_t)layer * 4096 + (size_t)osel * 2048;
        if (a32) {
#pragma unroll
            for (int i = tid; i < 2048; i += 512) {
                int r = i >> 4, c = i & 15;
                int grow = tile * 128 + r;
                unsigned w[4] = {0u, 0u, 0u, 0u};
                if (grow < N) {
                    const float4* ap = (const float4*)(a32 + (size_t)grow * D + c * 8);
                    float4 f0 = ap[0], f1 = ap[1];
                    __half2 h;
                    h = __floats2half2_rn(f0.x, f0.y); w[0] = *(unsigned*)&h;
                    h = __floats2half2_rn(f0.z, f0.w); w[1] = *(unsigned*)&h;
                    h = __floats2half2_rn(f1.x, f1.y); w[2] = *(unsigned*)&h;
                    h = __floats2half2_rn(f1.z, f1.w); w[3] = *(unsigned*)&h;
                }
                smem4[A4  + r * RS16 + c] = make_uint4(w[0], w[1], w[2], w[3]);
                smem4[WH4 + r * RS16 + c] = wh[i];
                smem4[WL4 + r * RS16 + c] = wl[i];
            }
        } else {
            const uint4* ga = g_x16 + (size_t)tile * 2048;
#pragma unroll
            for (int i = tid; i < 2048; i += 512) {
                int r = i >> 4, c = i & 15;
                smem4[A4  + r * RS16 + c] = ga[i];
                smem4[WH4 + r * RS16 + c] = wh[i];
                smem4[WL4 + r * RS16 + c] = wl[i];
            }
        }
    }
    __syncthreads();

    const uint32_t sb = smem_u32(smem4);
    const uint32_t aoff = (uint32_t)((mrow + (lane & 15)) * RSB + (lane >> 4) * 16);
    const uint32_t a0 = sb + A4 * 16 + aoff;
    const uint32_t a1 = a0 + 16 * RSB;
    const int msel = lane >> 3;
    const uint32_t woff = (uint32_t)((ncol + ((msel >> 1) * 8) + (lane & 7)) * RSB +
                                     (msel & 1) * 16);
    const uint32_t wH0 = sb + WH4 * 16 + woff;
    const uint32_t wH1 = wH0 + 16 * RSB;
    const uint32_t wL0 = sb + WL4 * 16 + woff;
    const uint32_t wL1 = wL0 + 16 * RSB;

    float acc[2][4][4];
#pragma unroll
    for (int mt = 0; mt < 2; mt++)
#pragma unroll
        for (int nt = 0; nt < 4; nt++)
#pragma unroll
            for (int i = 0; i < 4; i++) acc[mt][nt][i] = 0.f;

#pragma unroll
    for (int kc = 0; kc < 8; kc++) {
        const uint32_t kb = kc * 32;
        unsigned af[2][4], whf[2][4], wlf[2][4];
        ldsm4(af[0], a0 + kb); ldsm4(af[1], a1 + kb);
        ldsm4(whf[0], wH0 + kb); ldsm4(whf[1], wH1 + kb);
        ldsm4(wlf[0], wL0 + kb); ldsm4(wlf[1], wL1 + kb);
#pragma unroll
        for (int mt = 0; mt < 2; mt++)
#pragma unroll
            for (int nt = 0; nt < 4; nt++) {
                const unsigned* bh = &whf[nt >> 1][(nt & 1) * 2];
                const unsigned* bl = &wlf[nt >> 1][(nt & 1) * 2];
                mma16816(acc[mt][nt], af[mt], bh);
                mma16816(acc[mt][nt], af[mt], bl);
            }
    }

    // ---- store -------------------------------------------------------------
    const int q = lane & 3, g = lane >> 2;
    if (osel == 0) {
        __half* xp = (__half*)g_xl16;
#pragma unroll
        for (int nt = 0; nt < 4; nt++) {
            int col = ncol + nt * 8 + q * 2;
#pragma unroll
            for (int mt = 0; mt < 2; mt++) {
                int r = tile * 128 + mrow + mt * 16 + g;
                if (r < N)
                    *(__half2*)(xp + (size_t)r * D + col) =
                        __floats2half2_rn(acc[mt][nt][0], acc[mt][nt][1]);
                if (r + 8 < N)
                    *(__half2*)(xp + (size_t)(r + 8) * D + col) =
                        __floats2half2_rn(acc[mt][nt][2], acc[mt][nt][3]);
            }
        }
    } else {
#pragma unroll
        for (int nt = 0; nt < 4; nt++) {
            int col = ncol + nt * 8 + q * 2;
            float b0 = __ldg(bias + col), b1 = __ldg(bias + col + 1);
#pragma unroll
            for (int mt = 0; mt < 2; mt++) {
                int r = tile * 128 + mrow + mt * 16 + g;
                if (r < N) {
                    float2 v; v.x = acc[mt][nt][0] + b0; v.y = acc[mt][nt][1] + b1;
                    *(float2*)(selfp + (size_t)r * D + col) = v;
                }
                if (r + 8 < N) {
                    float2 v; v.x = acc[mt][nt][2] + b0; v.y = acc[mt][nt][3] + b1;
                    *(float2*)(selfp + (size_t)(r + 8) * D + col) = v;
                }
            }
        }
    }
}

// ---------------- CSR pull: out = [relu](self + mean_agg(xl16)) -------------
// warp per node; fp16 gather, fp32 accumulate; unroll-by-4 for MLP
__global__ void pull_kernel(float* __restrict__ out32, int writeStage,
                            int N, int Npad, int doRelu) {
    const int lane = threadIdx.x & 31;
    long long w  = (blockIdx.x * (long long)blockDim.x + threadIdx.x) >> 5;
    long long nw = ((long long)gridDim.x * blockDim.x) >> 5;

    uint2* stage = (uint2*)g_x16;

    for (long long node = w; node < Npad; node += nw) {
        if (node < N) {
            const int beg = g_off[node], end = g_off[node + 1];
            float4 acc = make_float4(0.f, 0.f, 0.f, 0.f);
            int e = beg;
            for (; e + 4 <= end; e += 4) {
                int s0 = __ldg(g_csr + e + 0);
                int s1 = __ldg(g_csr + e + 1);
                int s2 = __ldg(g_csr + e + 2);
                int s3 = __ldg(g_csr + e + 3);
                uint2 m0 = g_xl16[(size_t)s0 * 32 + lane];
                uint2 m1 = g_xl16[(size_t)s1 * 32 + lane];
                uint2 m2 = g_xl16[(size_t)s2 * 32 + lane];
                uint2 m3 = g_xl16[(size_t)s3 * 32 + lane];
                float2 f;
                f = __half22float2(*(__half2*)&m0.x); acc.x += f.x; acc.y += f.y;
                f = __half22float2(*(__half2*)&m0.y); acc.z += f.x; acc.w += f.y;
                f = __half22float2(*(__half2*)&m1.x); acc.x += f.x; acc.y += f.y;
                f = __half22float2(*(__half2*)&m1.y); acc.z += f.x; acc.w += f.y;
                f = __half22float2(*(__half2*)&m2.x); acc.x += f.x; acc.y += f.y;
                f = __half22float2(*(__half2*)&m2.y); acc.z += f.x; acc.w += f.y;
                f = __half22float2(*(__half2*)&m3.x); acc.x += f.x; acc.y += f.y;
                f = __half22float2(*(__half2*)&m3.y); acc.z += f.x; acc.w += f.y;
            }
            for (; e < end; e++) {
                int s = __ldg(g_csr + e);
                uint2 m = g_xl16[(size_t)s * 32 + lane];
                float2 f0 = __half22float2(*(__half2*)&m.x);
                float2 f1 = __half22float2(*(__half2*)&m.y);
                acc.x += f0.x; acc.y += f0.y; acc.z += f1.x; acc.w += f1.y;
            }
            float inv = g_inv[node];
            float4 sv = *(const float4*)(g_self + (size_t)node * D + lane * 4);
            float4 o;
            o.x = sv.x + acc.x * inv; o.y = sv.y + acc.y * inv;
            o.z = sv.z + acc.z * inv; o.w = sv.w + acc.w * inv;
            if (doRelu) {
                o.x = fmaxf(o.x, 0.f); o.y = fmaxf(o.y, 0.f);
                o.z = fmaxf(o.z, 0.f); o.w = fmaxf(o.w, 0.f);
            }
            if (out32)
                *(float4*)(out32 + (size_t)node * D + lane * 4) = o;
            if (writeStage) {
                uint2 p;
                __half2 h0 = __floats2half2_rn(o.x, o.y);
                __half2 h1 = __floats2half2_rn(o.z, o.w);
                p.x = *(unsigned*)&h0; p.y = *(unsigned*)&h1;
                stage[(size_t)node * 32 + lane] = p;
            }
        } else if (writeStage) {
            stage[(size_t)node * 32 + lane] = make_uint2(0u, 0u);
        }
    }
}

// ---------------- launch ------------------------------------------------------
extern "C" void kernel_launch(void* const* d_in, const int* in_sizes, int n_in,
                              void* d_out, int out_size) {
    const float* x    = (const float*)d_in[0];
    const void*  edge = d_in[1];
    const float* Wl1  = (const float*)d_in[2];
    const float* Wr1  = (const float*)d_in[3];
    const float* b1   = (const float*)d_in[4];
    const float* Wl2  = (const float*)d_in[5];
    const float* Wr2  = (const float*)d_in[6];
    const float* b2   = (const float*)d_in[7];
    float* out = (float*)d_out;

    const int N = in_sizes[0] / D;
    const int E = in_sizes[1] / 2;
    const int tiles = (N + 127) / 128;
    const int Npad = tiles * 128;
    const int scanBlocks = (N + 255) / 256;

    float* self;
    cudaGetSymbolAddress((void**)&self, g_self);

    cudaFuncSetAttribute(gemm_tc_kernel,
                         cudaFuncAttributeMaxDynamicSharedMemorySize, SMEMB);

    // ---- graph preprocessing ----
    prep_kernel<<<scanBlocks, 256>>>(edge, N);
    deg_kernel<<<2048, 256>>>(edge, E);
    scan1_kernel<<<scanBlocks, 256>>>(N);
    scan2_kernel<<<1, 512>>>(scanBlocks);
    scan3_kernel<<<scanBlocks, 256>>>(N, E);
    build_csr_kernel<<<2048, 256>>>(edge, E);

    // ---- weight conversion ----
    conv_w_kernel<<<32, 256>>>(Wl1, Wr1, Wl2, Wr2);

    dim3 ggrid(tiles, 2);

    // ---- layer 1 (A = fp32 x, converted in-kernel) ----
    gemm_tc_kernel<<<ggrid, 512, SMEMB>>>(b1, 0, self, N, x);
    pull_kernel<<<tiles * 16, 256>>>(nullptr, /*stage=*/1, N, Npad, /*relu=*/1);

    // ---- layer 2 (A = staged fp16 h) ----
    gemm_tc_kernel<<<ggrid, 512, SMEMB>>>(b2, 1, self, N, nullptr);
    pull_kernel<<<tiles * 16, 256>>>(out, /*stage=*/0, N, Npad, /*relu=*/0);
}

// round 7
// speedup vs baseline: 2.8157x; 1.0164x over previous
#include <cuda_runtime.h>
#include <cuda_fp16.h>
#include <cstdint>

#define D 128
#define MAXN 100000
#define MAXE 1600000
#define MAXTILES ((MAXN + 127) / 128)   // 782

// ---------------- scratch (device globals; no allocations allowed) ----------
__device__ float g_inv [MAXN];                     // 1/max(deg,1)
__device__ int   g_cnt [MAXN];                     // degree histogram
__device__ int   g_off [MAXN + 1];                 // CSR offsets
__device__ int   g_cur [MAXN];                     // fill cursors
__device__ int   g_csr [MAXE];                     // src indices bucketed by dst
__device__ float g_self[(size_t)MAXN * D];         // A @ Wr^T + b (self path)
__device__ uint2 g_xl16[(size_t)MAXN * 32];        // messages A@Wl^T, fp16 rows
__device__ int   g_is64;
// fp16 staging, row-major [row][128] fp16 (16 uint4 per row) — layer-2 GEMM input
__device__ uint4 g_x16[(size_t)MAXTILES * 2048];
__device__ uint4 g_wh[2 * 4096];   // per layer: [Wl;Wr] stacked = 256 rows, fp16 hi
__device__ uint4 g_wl[2 * 4096];   // fp16 lo
__device__ int   g_bsum[512];

// ---------------- streams/events for fork-join capture ----------------------
static cudaStream_t s_side = nullptr;
static cudaEvent_t  s_fork = nullptr, s_join = nullptr;
namespace {
struct SideInit {
    SideInit() {
        cudaStreamCreateWithFlags(&s_side, cudaStreamNonBlocking);
        cudaEventCreateWithFlags(&s_fork, cudaEventDisableTiming);
        cudaEventCreateWithFlags(&s_join, cudaEventDisableTiming);
    }
};
SideInit s_sideInit;
}

// ---------------- small helpers ---------------------------------------------
__device__ __forceinline__ int load_idx(const void* p, int is64, long long i) {
    if (is64) return (int)((const long long*)p)[i];
    return ((const int*)p)[i];
}

// probe edge dtype + zero degree histogram
__global__ void prep_kernel(const void* idx, int N) {
    int i = blockIdx.x * blockDim.x + threadIdx.x;
    if (i < N) g_cnt[i] = 0;
    if (i == 0) {
        const unsigned int* w = (const unsigned int*)idx;
        int all0 = 1;
        for (int k = 0; k < 128; k++)
            if (w[2 * k + 1] != 0u) { all0 = 0; break; }
        g_is64 = all0;
    }
}

__global__ void deg_kernel(const void* __restrict__ edge, int E) {
    int is64 = g_is64;
    long long stride = (long long)gridDim.x * blockDim.x;
    for (long long e = blockIdx.x * (long long)blockDim.x + threadIdx.x;
         e < E; e += stride) {
        int d = load_idx(edge, is64, (long long)E + e);
        atomicAdd(&g_cnt[d], 1);
    }
}

// ---- 3-stage exclusive scan of g_cnt -> g_off (+g_cur, g_inv) --------------
__global__ void scan1_kernel(int N) {
    __shared__ int sh[256];
    int i = blockIdx.x * 256 + threadIdx.x;
    sh[threadIdx.x] = (i < N) ? g_cnt[i] : 0;
    __syncthreads();
#pragma unroll
    for (int s = 128; s > 0; s >>= 1) {
        if (threadIdx.x < s) sh[threadIdx.x] += sh[threadIdx.x + s];
        __syncthreads();
    }
    if (threadIdx.x == 0) g_bsum[blockIdx.x] = sh[0];
}

// parallel exclusive scan of g_bsum[0..nb) — one 512-thread block
__global__ void scan2_kernel(int nb) {
    __shared__ int sh[512];
    int t = threadIdx.x;
    int v = (t < nb) ? g_bsum[t] : 0;
    sh[t] = v;
    __syncthreads();
#pragma unroll
    for (int s = 1; s < 512; s <<= 1) {
        int u = (t >= s) ? sh[t - s] : 0;
        __syncthreads();
        sh[t] += u;
        __syncthreads();
    }
    if (t < nb) g_bsum[t] = sh[t] - v;   // exclusive
}

__global__ void scan3_kernel(int N, int E) {
    __shared__ int sh[256];
    int i = blockIdx.x * 256 + threadIdx.x;
    int v = (i < N) ? g_cnt[i] : 0;
    sh[threadIdx.x] = v;
    __syncthreads();
#pragma unroll
    for (int s = 1; s < 256; s <<= 1) {
        int t = (threadIdx.x >= s) ? sh[threadIdx.x - s] : 0;
        __syncthreads();
        sh[threadIdx.x] += t;
        __syncthreads();
    }
    if (i < N) {
        int excl = g_bsum[blockIdx.x] + sh[threadIdx.x] - v;
        g_off[i] = excl;
        g_cur[i] = excl;
        g_inv[i] = 1.0f / fmaxf((float)v, 1.0f);
    }
    if (i == N - 1) g_off[N] = E;
}

__global__ void build_csr_kernel(const void* __restrict__ edge, int E) {
    int is64 = g_is64;
    long long stride = (long long)gridDim.x * blockDim.x;
    for (long long e = blockIdx.x * (long long)blockDim.x + threadIdx.x;
         e < E; e += stride) {
        int s = load_idx(edge, is64, e);
        int d = load_idx(edge, is64, (long long)E + e);
        int pos = atomicAdd(&g_cur[d], 1);
        g_csr[pos] = s;
    }
}

// ---------------- weight conversion: fp32 -> fp16 hi/lo ---------------------
__global__ void conv_w_kernel(const float* __restrict__ W0, const float* __restrict__ W1,
                              const float* __restrict__ W2, const float* __restrict__ W3) {
    int c = blockIdx.x * blockDim.x + threadIdx.x;   // 0 .. 4*2048-1
    if (c >= 4 * 2048) return;
    int which = c >> 11;
    int local = c & 2047;
    int row = local >> 4, kc = local & 15;
    const float* W = (which == 0) ? W0 : (which == 1) ? W1 : (which == 2) ? W2 : W3;
    const float4* ap = (const float4*)(W + (size_t)row * D + kc * 8);
    float4 a = ap[0], b = ap[1];
    float v[8] = {a.x, a.y, a.z, a.w, b.x, b.y, b.z, b.w};
    unsigned hw[4], lw[4];
#pragma unroll
    for (int i = 0; i < 4; i++) {
        __half h0 = __float2half_rn(v[2*i]);
        __half h1 = __float2half_rn(v[2*i+1]);
        __half l0 = __float2half_rn(v[2*i] - __half2float(h0));
        __half l1 = __float2half_rn(v[2*i+1] - __half2float(h1));
        hw[i] = (unsigned)__half_as_ushort(h0) | ((unsigned)__half_as_ushort(h1) << 16);
        lw[i] = (unsigned)__half_as_ushort(l0) | ((unsigned)__half_as_ushort(l1) << 16);
    }
    int layer = which >> 1, half = which & 1;
    long long o = (long long)layer * 4096 + half * 2048 + local;
    g_wh[o] = make_uint4(hw[0], hw[1], hw[2], hw[3]);
    g_wl[o] = make_uint4(lw[0], lw[1], lw[2], lw[3]);
}

// ---------------- mma.sync fp16 GEMM with ldmatrix ---------------------------
// grid (tiles, 2): y=0 -> xl16 = fp16(A@Wl^T) ; y=1 -> self = A@Wr^T + bias (fp32)
// A source: a32 (fp32, converted during staging) if non-null, else g_x16 (fp16)
__device__ __forceinline__ void mma16816(float* acc, const unsigned* a,
                                         const unsigned* b) {
    asm volatile(
        "mma.sync.aligned.m16n8k16.row.col.f32.f16.f16.f32 "
        "{%0,%1,%2,%3}, {%4,%5,%6,%7}, {%8,%9}, {%0,%1,%2,%3};"
        : "+f"(acc[0]), "+f"(acc[1]), "+f"(acc[2]), "+f"(acc[3])
        : "r"(a[0]), "r"(a[1]), "r"(a[2]), "r"(a[3]), "r"(b[0]), "r"(b[1]));
}
__device__ __forceinline__ void ldsm4(unsigned* r, uint32_t a) {
    asm volatile("ldmatrix.sync.aligned.m8n8.x4.shared.b16 {%0,%1,%2,%3}, [%4];"
        : "=r"(r[0]), "=r"(r[1]), "=r"(r[2]), "=r"(r[3]) : "r"(a));
}
__device__ __forceinline__ uint32_t smem_u32(const void* p) {
    uint32_t a;
    asm("{ .reg .u64 t; cvta.to.shared.u64 t, %1; cvt.u32.u64 %0, t; }"
        : "=r"(a) : "l"(p));
    return a;
}

// SMEM row = 272B (17 uint4): ldmatrix 8-row phases -> conflict-free
#define RS16 17
#define RSB  272
#define A4   0
#define WH4  2176
#define WL4  4352
#define SMEMB 104448

__global__ __launch_bounds__(512, 1)
void gemm_tc_kernel(const float* __restrict__ bias, int layer,
                    float* __restrict__ selfp, int N,
                    const float* __restrict__ a32) {
    extern __shared__ uint4 smem4[];

    const int tid  = threadIdx.x;
    const int wid  = tid >> 5;
    const int lane = tid & 31;
    const int tile = blockIdx.x;
    const int osel = blockIdx.y;

    const int mrow = (wid & 3) * 32;
    const int ncol = (wid >> 2) * 32;

    // ---- stage A and this output's W (hi/lo) ----
    {
        const uint4* wh = g_wh + (size_t)layer * 4096 + (size_t)osel * 2048;
        const uint4* wl = g_wl + (size_t)layer * 4096 + (size_t)osel * 2048;
        if (a32) {
#pragma unroll
            for (int i = tid; i < 2048; i += 512) {
                int r = i >> 4, c = i & 15;
                int grow = tile * 128 + r;
                unsigned w[4] = {0u, 0u, 0u, 0u};
                if (grow < N) {
                    const float4* ap = (const float4*)(a32 + (size_t)grow * D + c * 8);
                    float4 f0 = ap[0], f1 = ap[1];
                    __half2 h;
                    h = __floats2half2_rn(f0.x, f0.y); w[0] = *(unsigned*)&h;
                    h = __floats2half2_rn(f0.z, f0.w); w[1] = *(unsigned*)&h;
                    h = __floats2half2_rn(f1.x, f1.y); w[2] = *(unsigned*)&h;
                    h = __floats2half2_rn(f1.z, f1.w); w[3] = *(unsigned*)&h;
                }
                smem4[A4  + r * RS16 + c] = make_uint4(w[0], w[1], w[2], w[3]);
                smem4[WH4 + r * RS16 + c] = wh[i];
                smem4[WL4 + r * RS16 + c] = wl[i];
            }
        } else {
            const uint4* ga = g_x16 + (size_t)tile * 2048;
#pragma unroll
            for (int i = tid; i < 2048; i += 512) {
                int r = i >> 4, c = i & 15;
                smem4[A4  + r * RS16 + c] = ga[i];
                smem4[WH4 + r * RS16 + c] = wh[i];
                smem4[WL4 + r * RS16 + c] = wl[i];
            }
        }
    }
    __syncthreads();

    const uint32_t sb = smem_u32(smem4);
    const uint32_t aoff = (uint32_t)((mrow + (lane & 15)) * RSB + (lane >> 4) * 16);
    const uint32_t a0 = sb + A4 * 16 + aoff;
    const uint32_t a1 = a0 + 16 * RSB;
    const int msel = lane >> 3;
    const uint32_t woff = (uint32_t)((ncol + ((msel >> 1) * 8) + (lane & 7)) * RSB +
                                     (msel & 1) * 16);
    const uint32_t wH0 = sb + WH4 * 16 + woff;
    const uint32_t wH1 = wH0 + 16 * RSB;
    const uint32_t wL0 = sb + WL4 * 16 + woff;
    const uint32_t wL1 = wL0 + 16 * RSB;

    float acc[2][4][4];
#pragma unroll
    for (int mt = 0; mt < 2; mt++)
#pragma unroll
        for (int nt = 0; nt < 4; nt++)
#pragma unroll
            for (int i = 0; i < 4; i++) acc[mt][nt][i] = 0.f;

#pragma unroll
    for (int kc = 0; kc < 8; kc++) {
        const uint32_t kb = kc * 32;
        unsigned af[2][4], whf[2][4], wlf[2][4];
        ldsm4(af[0], a0 + kb); ldsm4(af[1], a1 + kb);
        ldsm4(whf[0], wH0 + kb); ldsm4(whf[1], wH1 + kb);
        ldsm4(wlf[0], wL0 + kb); ldsm4(wlf[1], wL1 + kb);
#pragma unroll
        for (int mt = 0; mt < 2; mt++)
#pragma unroll
            for (int nt = 0; nt < 4; nt++) {
                const unsigned* bh = &whf[nt >> 1][(nt & 1) * 2];
                const unsigned* bl = &wlf[nt >> 1][(nt & 1) * 2];
                mma16816(acc[mt][nt], af[mt], bh);
                mma16816(acc[mt][nt], af[mt], bl);
            }
    }

    // ---- store -------------------------------------------------------------
    const int q = lane & 3, g = lane >> 2;
    if (osel == 0) {
        __half* xp = (__half*)g_xl16;
#pragma unroll
        for (int nt = 0; nt < 4; nt++) {
            int col = ncol + nt * 8 + q * 2;
#pragma unroll
            for (int mt = 0; mt < 2; mt++) {
                int r = tile * 128 + mrow + mt * 16 + g;
                if (r < N)
                    *(__half2*)(xp + (size_t)r * D + col) =
                        __floats2half2_rn(acc[mt][nt][0], acc[mt][nt][1]);
                if (r + 8 < N)
                    *(__half2*)(xp + (size_t)(r + 8) * D + col) =
                        __floats2half2_rn(acc[mt][nt][2], acc[mt][nt][3]);
            }
        }
    } else {
#pragma unroll
        for (int nt = 0; nt < 4; nt++) {
            int col = ncol + nt * 8 + q * 2;
            float b0 = __ldg(bias + col), b1 = __ldg(bias + col + 1);
#pragma unroll
            for (int mt = 0; mt < 2; mt++) {
                int r = tile * 128 + mrow + mt * 16 + g;
                if (r < N) {
                    float2 v; v.x = acc[mt][nt][0] + b0; v.y = acc[mt][nt][1] + b1;
                    *(float2*)(selfp + (size_t)r * D + col) = v;
                }
                if (r + 8 < N) {
                    float2 v; v.x = acc[mt][nt][2] + b0; v.y = acc[mt][nt][3] + b1;
                    *(float2*)(selfp + (size_t)(r + 8) * D + col) = v;
                }
            }
        }
    }
}

// ---------------- CSR pull: out = [relu](self + mean_agg(xl16)) -------------
// warp per node; fp16 gather, fp32 accumulate; unroll-by-4 for MLP
__global__ void pull_kernel(float* __restrict__ out32, int writeStage,
                            int N, int Npad, int doRelu) {
    const int lane = threadIdx.x & 31;
    long long w  = (blockIdx.x * (long long)blockDim.x + threadIdx.x) >> 5;
    long long nw = ((long long)gridDim.x * blockDim.x) >> 5;

    uint2* stage = (uint2*)g_x16;

    for (long long node = w; node < Npad; node += nw) {
        if (node < N) {
            const int beg = g_off[node], end = g_off[node + 1];
            float4 acc = make_float4(0.f, 0.f, 0.f, 0.f);
            int e = beg;
            for (; e + 4 <= end; e += 4) {
                int s0 = __ldg(g_csr + e + 0);
                int s1 = __ldg(g_csr + e + 1);
                int s2 = __ldg(g_csr + e + 2);
                int s3 = __ldg(g_csr + e + 3);
                uint2 m0 = g_xl16[(size_t)s0 * 32 + lane];
                uint2 m1 = g_xl16[(size_t)s1 * 32 + lane];
                uint2 m2 = g_xl16[(size_t)s2 * 32 + lane];
                uint2 m3 = g_xl16[(size_t)s3 * 32 + lane];
                float2 f;
                f = __half22float2(*(__half2*)&m0.x); acc.x += f.x; acc.y += f.y;
                f = __half22float2(*(__half2*)&m0.y); acc.z += f.x; acc.w += f.y;
                f = __half22float2(*(__half2*)&m1.x); acc.x += f.x; acc.y += f.y;
                f = __half22float2(*(__half2*)&m1.y); acc.z += f.x; acc.w += f.y;
                f = __half22float2(*(__half2*)&m2.x); acc.x += f.x; acc.y += f.y;
                f = __half22float2(*(__half2*)&m2.y); acc.z += f.x; acc.w += f.y;
                f = __half22float2(*(__half2*)&m3.x); acc.x += f.x; acc.y += f.y;
                f = __half22float2(*(__half2*)&m3.y); acc.z += f.x; acc.w += f.y;
            }
            for (; e < end; e++) {
                int s = __ldg(g_csr + e);
                uint2 m = g_xl16[(size_t)s * 32 + lane];
                float2 f0 = __half22float2(*(__half2*)&m.x);
                float2 f1 = __half22float2(*(__half2*)&m.y);
                acc.x += f0.x; acc.y += f0.y; acc.z += f1.x; acc.w += f1.y;
            }
            float inv = g_inv[node];
            float4 sv = *(const float4*)(g_self + (size_t)node * D + lane * 4);
            float4 o;
            o.x = sv.x + acc.x * inv; o.y = sv.y + acc.y * inv;
            o.z = sv.z + acc.z * inv; o.w = sv.w + acc.w * inv;
            if (doRelu) {
                o.x = fmaxf(o.x, 0.f); o.y = fmaxf(o.y, 0.f);
                o.z = fmaxf(o.z, 0.f); o.w = fmaxf(o.w, 0.f);
            }
            if (out32)
                *(float4*)(out32 + (size_t)node * D + lane * 4) = o;
            if (writeStage) {
                uint2 p;
                __half2 h0 = __floats2half2_rn(o.x, o.y);
                __half2 h1 = __floats2half2_rn(o.z, o.w);
                p.x = *(unsigned*)&h0; p.y = *(unsigned*)&h1;
                stage[(size_t)node * 32 + lane] = p;
            }
        } else if (writeStage) {
            stage[(size_t)node * 32 + lane] = make_uint2(0u, 0u);
        }
    }
}

// ---------------- launch ------------------------------------------------------
extern "C" void kernel_launch(void* const* d_in, const int* in_sizes, int n_in,
                              void* d_out, int out_size) {
    const float* x    = (const float*)d_in[0];
    const void*  edge = d_in[1];
    const float* Wl1  = (const float*)d_in[2];
    const float* Wr1  = (const float*)d_in[3];
    const float* b1   = (const float*)d_in[4];
    const float* Wl2  = (const float*)d_in[5];
    const float* Wr2  = (const float*)d_in[6];
    const float* b2   = (const float*)d_in[7];
    float* out = (float*)d_out;

    const int N = in_sizes[0] / D;
    const int E = in_sizes[1] / 2;
    const int tiles = (N + 127) / 128;
    const int Npad = tiles * 128;
    const int scanBlocks = (N + 255) / 256;

    float* self;
    cudaGetSymbolAddress((void**)&self, g_self);

    cudaFuncSetAttribute(gemm_tc_kernel,
                         cudaFuncAttributeMaxDynamicSharedMemorySize, SMEMB);

    dim3 ggrid(tiles, 2);

    // ---- fork: side branch = conv_w -> gemm1 (independent of CSR build) ----
    cudaEventRecord(s_fork, 0);                       // legacy default stream
    cudaStreamWaitEvent(s_side, s_fork, 0);
    conv_w_kernel<<<32, 256, 0, s_side>>>(Wl1, Wr1, Wl2, Wr2);
    gemm_tc_kernel<<<ggrid, 512, SMEMB, s_side>>>(b1, 0, self, N, x);
    cudaEventRecord(s_join, s_side);

    // ---- main branch: graph preprocessing ----
    prep_kernel<<<scanBlocks, 256>>>(edge, N);
    deg_kernel<<<2048, 256>>>(edge, E);
    scan1_kernel<<<scanBlocks, 256>>>(N);
    scan2_kernel<<<1, 512>>>(scanBlocks);
    scan3_kernel<<<scanBlocks, 256>>>(N, E);
    build_csr_kernel<<<2048, 256>>>(edge, E);

    // ---- join, then the dependent tail ----
    cudaStreamWaitEvent(0, s_join, 0);
    pull_kernel<<<tiles * 16, 256>>>(nullptr, /*stage=*/1, N, Npad, /*relu=*/1);
    gemm_tc_kernel<<<ggrid, 512, SMEMB>>>(b2, 1, self, N, nullptr);
    pull_kernel<<<tiles * 16, 256>>>(out, /*stage=*/0, N, Npad, /*relu=*/0);
}

// round 8
// speedup vs baseline: 3.2669x; 1.1603x over previous
#include <cuda_runtime.h>
#include <cuda_fp16.h>
#include <cstdint>

#define D 128
#define MAXN 100000
#define MAXE 1600000
#define MAXTILES ((MAXN + 127) / 128)   // 782

// ---------------- scratch (device globals; no allocations allowed) ----------
__device__ float g_inv [MAXN];                     // 1/max(deg,1)
__device__ int   g_cnt [MAXN];                     // degree histogram
__device__ int   g_off [MAXN + 1];                 // CSR offsets
__device__ int   g_cur [MAXN];                     // fill cursors
__device__ int   g_csr [MAXE];                     // src indices bucketed by dst
__device__ uint2 g_self16[(size_t)MAXN * 32];      // A @ Wr^T + b, fp16 rows
__device__ uint2 g_xl16[(size_t)MAXN * 32];        // messages A@Wl^T, fp16 rows
__device__ int   g_is64;
// fp16 staging, row-major [row][128] fp16 (16 uint4 per row) — layer-2 GEMM input
__device__ uint4 g_x16[(size_t)MAXTILES * 2048];
__device__ uint4 g_w16[2 * 4096];  // per layer: [Wl;Wr] stacked = 256 rows, fp16
__device__ int   g_bsum[512];

// ---------------- streams/events for fork-join capture ----------------------
static cudaStream_t s_side = nullptr;
static cudaEvent_t  s_fork = nullptr, s_join = nullptr;
namespace {
struct SideInit {
    SideInit() {
        cudaStreamCreateWithFlags(&s_side, cudaStreamNonBlocking);
        cudaEventCreateWithFlags(&s_fork, cudaEventDisableTiming);
        cudaEventCreateWithFlags(&s_join, cudaEventDisableTiming);
    }
};
SideInit s_sideInit;
}

// ---------------- small helpers ---------------------------------------------
__device__ __forceinline__ int load_idx(const void* p, int is64, long long i) {
    if (is64) return (int)((const long long*)p)[i];
    return ((const int*)p)[i];
}

// probe edge dtype + zero degree histogram
__global__ void prep_kernel(const void* idx, int N) {
    int i = blockIdx.x * blockDim.x + threadIdx.x;
    if (i < N) g_cnt[i] = 0;
    if (i == 0) {
        const unsigned int* w = (const unsigned int*)idx;
        int all0 = 1;
        for (int k = 0; k < 128; k++)
            if (w[2 * k + 1] != 0u) { all0 = 0; break; }
        g_is64 = all0;
    }
}

__global__ void deg_kernel(const void* __restrict__ edge, int E) {
    int is64 = g_is64;
    long long stride = (long long)gridDim.x * blockDim.x;
    for (long long e = blockIdx.x * (long long)blockDim.x + threadIdx.x;
         e < E; e += stride) {
        int d = load_idx(edge, is64, (long long)E + e);
        atomicAdd(&g_cnt[d], 1);
    }
}

// ---- scan: stage1 block sums, stage2 fused into stage3 ---------------------
__global__ void scan1_kernel(int N) {
    __shared__ int sh[256];
    int i = blockIdx.x * 256 + threadIdx.x;
    sh[threadIdx.x] = (i < N) ? g_cnt[i] : 0;
    __syncthreads();
#pragma unroll
    for (int s = 128; s > 0; s >>= 1) {
        if (threadIdx.x < s) sh[threadIdx.x] += sh[threadIdx.x + s];
        __syncthreads();
    }
    if (threadIdx.x == 0) g_bsum[blockIdx.x] = sh[0];
}

__global__ void scan3_kernel(int N, int E) {
    __shared__ int sh[256];
    __shared__ int red[256];
    const int t = threadIdx.x;
    const int i = blockIdx.x * 256 + t;

    // block-exclusive base = sum of bsum[j], j < blockIdx.x
    int acc = 0;
    for (int j = t; j < blockIdx.x; j += 256) acc += g_bsum[j];
    red[t] = acc;
    __syncthreads();
#pragma unroll
    for (int s = 128; s > 0; s >>= 1) {
        if (t < s) red[t] += red[t + s];
        __syncthreads();
    }
    const int base = red[0];

    int v = (i < N) ? g_cnt[i] : 0;
    sh[t] = v;
    __syncthreads();
#pragma unroll
    for (int s = 1; s < 256; s <<= 1) {
        int u = (t >= s) ? sh[t - s] : 0;
        __syncthreads();
        sh[t] += u;
        __syncthreads();
    }
    if (i < N) {
        int excl = base + sh[t] - v;
        g_off[i] = excl;
        g_cur[i] = excl;
        g_inv[i] = 1.0f / fmaxf((float)v, 1.0f);
    }
    if (i == N - 1) g_off[N] = E;
}

__global__ void build_csr_kernel(const void* __restrict__ edge, int E) {
    int is64 = g_is64;
    long long stride = (long long)gridDim.x * blockDim.x;
    for (long long e = blockIdx.x * (long long)blockDim.x + threadIdx.x;
         e < E; e += stride) {
        int s = load_idx(edge, is64, e);
        int d = load_idx(edge, is64, (long long)E + e);
        int pos = atomicAdd(&g_cur[d], 1);
        g_csr[pos] = s;
    }
}

// ---------------- weight conversion: fp32 -> fp16 ---------------------------
__global__ void conv_w_kernel(const float* __restrict__ W0, const float* __restrict__ W1,
                              const float* __restrict__ W2, const float* __restrict__ W3) {
    int c = blockIdx.x * blockDim.x + threadIdx.x;   // 0 .. 4*2048-1
    if (c >= 4 * 2048) return;
    int which = c >> 11;
    int local = c & 2047;
    int row = local >> 4, kc = local & 15;
    const float* W = (which == 0) ? W0 : (which == 1) ? W1 : (which == 2) ? W2 : W3;
    const float4* ap = (const float4*)(W + (size_t)row * D + kc * 8);
    float4 a = ap[0], b = ap[1];
    float v[8] = {a.x, a.y, a.z, a.w, b.x, b.y, b.z, b.w};
    unsigned hw[4];
#pragma unroll
    for (int i = 0; i < 4; i++) {
        __half2 h = __floats2half2_rn(v[2*i], v[2*i+1]);
        hw[i] = *(unsigned*)&h;
    }
    int layer = which >> 1, half = which & 1;
    long long o = (long long)layer * 4096 + half * 2048 + local;
    g_w16[o] = make_uint4(hw[0], hw[1], hw[2], hw[3]);
}

// ---------------- mma.sync fp16 GEMM with ldmatrix ---------------------------
// grid (tiles, 2): y=0 -> xl16 = fp16(A@Wl^T) ; y=1 -> self16 = fp16(A@Wr^T + b)
// A source: a32 (fp32, converted during staging) if non-null, else g_x16 (fp16)
__device__ __forceinline__ void mma16816(float* acc, const unsigned* a,
                                         const unsigned* b) {
    asm volatile(
        "mma.sync.aligned.m16n8k16.row.col.f32.f16.f16.f32 "
        "{%0,%1,%2,%3}, {%4,%5,%6,%7}, {%8,%9}, {%0,%1,%2,%3};"
        : "+f"(acc[0]), "+f"(acc[1]), "+f"(acc[2]), "+f"(acc[3])
        : "r"(a[0]), "r"(a[1]), "r"(a[2]), "r"(a[3]), "r"(b[0]), "r"(b[1]));
}
__device__ __forceinline__ void ldsm4(unsigned* r, uint32_t a) {
    asm volatile("ldmatrix.sync.aligned.m8n8.x4.shared.b16 {%0,%1,%2,%3}, [%4];"
        : "=r"(r[0]), "=r"(r[1]), "=r"(r[2]), "=r"(r[3]) : "r"(a));
}
__device__ __forceinline__ uint32_t smem_u32(const void* p) {
    uint32_t a;
    asm("{ .reg .u64 t; cvta.to.shared.u64 t, %1; cvt.u32.u64 %0, t; }"
        : "=r"(a) : "l"(p));
    return a;
}

// SMEM row = 272B (17 uint4): ldmatrix 8-row phases -> conflict-free
#define RS16 17
#define RSB  272
#define A4   0
#define W4   2176
#define SMEMB 69632

__global__ __launch_bounds__(512, 1)
void gemm_tc_kernel(const float* __restrict__ bias, int layer,
                    int N, const float* __restrict__ a32) {
    extern __shared__ uint4 smem4[];

    const int tid  = threadIdx.x;
    const int wid  = tid >> 5;
    const int lane = tid & 31;
    const int tile = blockIdx.x;
    const int osel = blockIdx.y;

    const int mrow = (wid & 3) * 32;
    const int ncol = (wid >> 2) * 32;

    // ---- stage A and this output's W ----
    {
        const uint4* w = g_w16 + (size_t)layer * 4096 + (size_t)osel * 2048;
        if (a32) {
#pragma unroll
            for (int i = tid; i < 2048; i += 512) {
                int r = i >> 4, c = i & 15;
                int grow = tile * 128 + r;
                unsigned wd[4] = {0u, 0u, 0u, 0u};
                if (grow < N) {
                    const float4* ap = (const float4*)(a32 + (size_t)grow * D + c * 8);
                    float4 f0 = ap[0], f1 = ap[1];
                    __half2 h;
                    h = __floats2half2_rn(f0.x, f0.y); wd[0] = *(unsigned*)&h;
                    h = __floats2half2_rn(f0.z, f0.w); wd[1] = *(unsigned*)&h;
                    h = __floats2half2_rn(f1.x, f1.y); wd[2] = *(unsigned*)&h;
                    h = __floats2half2_rn(f1.z, f1.w); wd[3] = *(unsigned*)&h;
                }
                smem4[A4 + r * RS16 + c] = make_uint4(wd[0], wd[1], wd[2], wd[3]);
                smem4[W4 + r * RS16 + c] = w[i];
            }
        } else {
            const uint4* ga = g_x16 + (size_t)tile * 2048;
#pragma unroll
            for (int i = tid; i < 2048; i += 512) {
                int r = i >> 4, c = i & 15;
                smem4[A4 + r * RS16 + c] = ga[i];
                smem4[W4 + r * RS16 + c] = w[i];
            }
        }
    }
    __syncthreads();

    const uint32_t sb = smem_u32(smem4);
    const uint32_t aoff = (uint32_t)((mrow + (lane & 15)) * RSB + (lane >> 4) * 16);
    const uint32_t a0 = sb + A4 * 16 + aoff;
    const uint32_t a1 = a0 + 16 * RSB;
    const int msel = lane >> 3;
    const uint32_t woff = (uint32_t)((ncol + ((msel >> 1) * 8) + (lane & 7)) * RSB +
                                     (msel & 1) * 16);
    const uint32_t w0 = sb + W4 * 16 + woff;
    const uint32_t w1 = w0 + 16 * RSB;

    float acc[2][4][4];
#pragma unroll
    for (int mt = 0; mt < 2; mt++)
#pragma unroll
        for (int nt = 0; nt < 4; nt++)
#pragma unroll
            for (int i = 0; i < 4; i++) acc[mt][nt][i] = 0.f;

#pragma unroll
    for (int kc = 0; kc < 8; kc++) {
        const uint32_t kb = kc * 32;
        unsigned af[2][4], wf[2][4];
        ldsm4(af[0], a0 + kb); ldsm4(af[1], a1 + kb);
        ldsm4(wf[0], w0 + kb); ldsm4(wf[1], w1 + kb);
#pragma unroll
        for (int mt = 0; mt < 2; mt++)
#pragma unroll
            for (int nt = 0; nt < 4; nt++)
                mma16816(acc[mt][nt], af[mt], &wf[nt >> 1][(nt & 1) * 2]);
    }

    // ---- store (both outputs fp16) ------------------------------------------
    const int q = lane & 3, g = lane >> 2;
    __half* op = (__half*)(osel ? g_self16 : g_xl16);
#pragma unroll
    for (int nt = 0; nt < 4; nt++) {
        int col = ncol + nt * 8 + q * 2;
        float b0 = 0.f, b1 = 0.f;
        if (osel) { b0 = __ldg(bias + col); b1 = __ldg(bias + col + 1); }
#pragma unroll
        for (int mt = 0; mt < 2; mt++) {
            int r = tile * 128 + mrow + mt * 16 + g;
            if (r < N)
                *(__half2*)(op + (size_t)r * D + col) =
                    __floats2half2_rn(acc[mt][nt][0] + b0, acc[mt][nt][1] + b1);
            if (r + 8 < N)
                *(__half2*)(op + (size_t)(r + 8) * D + col) =
                    __floats2half2_rn(acc[mt][nt][2] + b0, acc[mt][nt][3] + b1);
        }
    }
}

// ---------------- CSR pull: out = [relu](self + mean_agg(xl16)) -------------
// warp per node; fp16 gather, fp32 accumulate; unroll-by-4 for MLP
__global__ void pull_kernel(float* __restrict__ out32, int writeStage,
                            int N, int Npad, int doRelu) {
    const int lane = threadIdx.x & 31;
    long long w  = (blockIdx.x * (long long)blockDim.x + threadIdx.x) >> 5;
    long long nw = ((long long)gridDim.x * blockDim.x) >> 5;

    uint2* stage = (uint2*)g_x16;

    for (long long node = w; node < Npad; node += nw) {
        if (node < N) {
            const int beg = g_off[node], end = g_off[node + 1];
            float4 acc = make_float4(0.f, 0.f, 0.f, 0.f);
            int e = beg;
            for (; e + 4 <= end; e += 4) {
                int s0 = __ldg(g_csr + e + 0);
                int s1 = __ldg(g_csr + e + 1);
                int s2 = __ldg(g_csr + e + 2);
                int s3 = __ldg(g_csr + e + 3);
                uint2 m0 = g_xl16[(size_t)s0 * 32 + lane];
                uint2 m1 = g_xl16[(size_t)s1 * 32 + lane];
                uint2 m2 = g_xl16[(size_t)s2 * 32 + lane];
                uint2 m3 = g_xl16[(size_t)s3 * 32 + lane];
                float2 f;
                f = __half22float2(*(__half2*)&m0.x); acc.x += f.x; acc.y += f.y;
                f = __half22float2(*(__half2*)&m0.y); acc.z += f.x; acc.w += f.y;
                f = __half22float2(*(__half2*)&m1.x); acc.x += f.x; acc.y += f.y;
                f = __half22float2(*(__half2*)&m1.y); acc.z += f.x; acc.w += f.y;
                f = __half22float2(*(__half2*)&m2.x); acc.x += f.x; acc.y += f.y;
                f = __half22float2(*(__half2*)&m2.y); acc.z += f.x; acc.w += f.y;
                f = __half22float2(*(__half2*)&m3.x); acc.x += f.x; acc.y += f.y;
                f = __half22float2(*(__half2*)&m3.y); acc.z += f.x; acc.w += f.y;
            }
            for (; e < end; e++) {
                int s = __ldg(g_csr + e);
                uint2 m = g_xl16[(size_t)s * 32 + lane];
                float2 f0 = __half22float2(*(__half2*)&m.x);
                float2 f1 = __half22float2(*(__half2*)&m.y);
                acc.x += f0.x; acc.y += f0.y; acc.z += f1.x; acc.w += f1.y;
            }
            float inv = g_inv[node];
            uint2 s16 = g_self16[(size_t)node * 32 + lane];
            float2 sv0 = __half22float2(*(__half2*)&s16.x);
            float2 sv1 = __half22float2(*(__half2*)&s16.y);
            float4 o;
            o.x = sv0.x + acc.x * inv; o.y = sv0.y + acc.y * inv;
            o.z = sv1.x + acc.z * inv; o.w = sv1.y + acc.w * inv;
            if (doRelu) {
                o.x = fmaxf(o.x, 0.f); o.y = fmaxf(o.y, 0.f);
                o.z = fmaxf(o.z, 0.f); o.w = fmaxf(o.w, 0.f);
            }
            if (out32)
                *(float4*)(out32 + (size_t)node * D + lane * 4) = o;
            if (writeStage) {
                uint2 p;
                __half2 h0 = __floats2half2_rn(o.x, o.y);
                __half2 h1 = __floats2half2_rn(o.z, o.w);
                p.x = *(unsigned*)&h0; p.y = *(unsigned*)&h1;
                stage[(size_t)node * 32 + lane] = p;
            }
        } else if (writeStage) {
            stage[(size_t)node * 32 + lane] = make_uint2(0u, 0u);
        }
    }
}

// ---------------- launch ------------------------------------------------------
extern "C" void kernel_launch(void* const* d_in, const int* in_sizes, int n_in,
                              void* d_out, int out_size) {
    const float* x    = (const float*)d_in[0];
    const void*  edge = d_in[1];
    const float* Wl1  = (const float*)d_in[2];
    const float* Wr1  = (const float*)d_in[3];
    const float* b1   = (const float*)d_in[4];
    const float* Wl2  = (const float*)d_in[5];
    const float* Wr2  = (const float*)d_in[6];
    const float* b2   = (const float*)d_in[7];
    float* out = (float*)d_out;

    const int N = in_sizes[0] / D;
    const int E = in_sizes[1] / 2;
    const int tiles = (N + 127) / 128;
    const int Npad = tiles * 128;
    const int scanBlocks = (N + 255) / 256;

    cudaFuncSetAttribute(gemm_tc_kernel,
                         cudaFuncAttributeMaxDynamicSharedMemorySize, SMEMB);

    dim3 ggrid(tiles, 2);

    // ---- fork: side branch = conv_w -> gemm1 (independent of CSR build) ----
    cudaEventRecord(s_fork, 0);                       // legacy default stream
    cudaStreamWaitEvent(s_side, s_fork, 0);
    conv_w_kernel<<<32, 256, 0, s_side>>>(Wl1, Wr1, Wl2, Wr2);
    gemm_tc_kernel<<<ggrid, 512, SMEMB, s_side>>>(b1, 0, N, x);
    cudaEventRecord(s_join, s_side);

    // ---- main branch: graph preprocessing ----
    prep_kernel<<<scanBlocks, 256>>>(edge, N);
    deg_kernel<<<2048, 256>>>(edge, E);
    scan1_kernel<<<scanBlocks, 256>>>(N);
    scan3_kernel<<<scanBlocks, 256>>>(N, E);
    build_csr_kernel<<<2048, 256>>>(edge, E);

    // ---- join, then the dependent tail ----
    cudaStreamWaitEvent(0, s_join, 0);
    pull_kernel<<<tiles * 16, 256>>>(nullptr, /*stage=*/1, N, Npad, /*relu=*/1);
    gemm_tc_kernel<<<ggrid, 512, SMEMB>>>(b2, 1, N, nullptr);
    pull_kernel<<<tiles * 16, 256>>>(out, /*stage=*/0, N, Npad, /*relu=*/0);
}